// round 7
// baseline (speedup 1.0000x reference)
#include <cuda_runtime.h>
#include <cuda_bf16.h>
#include <stdint.h>
#include <math.h>

#define D_    256
#define H_    8
#define HD_   32
#define NIMG_ 4096
#define NN    4112
#define BB    2
#define NKE_  64
#define MROWS (BB * NN)      /* 8224 */
#define NKD   (NN - NKE_)    /* 4048 */
#define NT1   32             /* ceil(4048/128) */
#define NTALL 33             /* 32 dense tiles + 1 mem tile */

// ---------------- global scratch (no allocs allowed) ----------------
__device__ __nv_bfloat16 g_qh[(size_t)BB * H_ * NN * HD_];
__device__ __nv_bfloat16 g_ql[(size_t)BB * H_ * NN * HD_];
__device__ __nv_bfloat16 g_kh[(size_t)BB * H_ * NN * HD_];
__device__ __nv_bfloat16 g_kl[(size_t)BB * H_ * NN * HD_];
// V stored TRANSPOSED: [b][h][d][key]
__device__ __nv_bfloat16 g_vh[(size_t)BB * H_ * HD_ * NN];
__device__ __nv_bfloat16 g_vl[(size_t)BB * H_ * HD_ * NN];
__device__ float g_ao[(size_t)MROWS * D_];

// ---------------- SMEM layout for attention (bytes) ----------------
// 3 KV buffers, each 32768: K packed hi|lo (16384) + VH(8192) + VL(8192)
#define SM_KV0    0
#define KV_STRIDE 32768
#define KV_VOFF   16384
// 2 P buffers, each 65536: PH(32768) + PL(32768)
#define SM_P0     98304
#define SM_P1     163840
#define P_LOFF    32768
#define SM_CTRL   229376
#define SM_TM     (SM_CTRL + 0)
#define SM_MBS    (SM_CTRL + 8)
#define SM_MBO    (SM_CTRL + 16)
#define SM_LSUM1  (SM_CTRL + 64)   /* 128 floats: 229440..229952 */
#define SM_LSUM2  (SM_CTRL + 576)  /* 128 floats: 229952..230464 */
#define SMEM_TOTAL 230528          /* fixed: covers LSUM2 end (230464) */

// TMEM columns: S0@0(128), S1@128(128), O1@256(32), O2@288(32), Q@320(32)
#define TM_S0 0
#define TM_S1 128
#define TM_O1 256
#define TM_O2 288
#define TM_Q  320

// idesc kind::f16: dtypeF32(1<<4) | aBF16(1<<7) | bBF16(1<<10) | (N/8)<<17 | (M/16)<<24
#define IDESC_QK 0x8200490u   /* M=128 N=128 */
#define IDESC_PV 0x8080490u   /* M=128 N=32  */

// scale: 1/sqrt(32) * log2(e)  (so softmax exp == exp2)
#define QSCALE (0.17677669529663687f * 1.4426950408889634f)

// ---------------- arch-portable helpers ----------------
__device__ __forceinline__ uint32_t smem_u32(const void* p) {
    uint32_t a;
    asm("{ .reg .u64 t; cvta.to.shared.u64 t, %1; cvt.u32.u64 %0, t; }" : "=r"(a) : "l"(p));
    return a;
}
__device__ __forceinline__ float ex2f(float x) {
    float y; asm("ex2.approx.ftz.f32 %0, %1;" : "=f"(y) : "f"(x)); return y;
}
__device__ __forceinline__ uint32_t swz(uint32_t b) { return b ^ ((b >> 3) & 0x70); }

// ---------------- tcgen05 helpers: sm_103a ONLY ----------------
#if defined(__CUDA_ARCH_FEAT_SM103_ALL)
__device__ __forceinline__ bool elect1() {
    uint32_t p;
    asm volatile("{ .reg .pred p; elect.sync _|p, 0xFFFFFFFF; selp.b32 %0, 1, 0, p; }" : "=r"(p));
    return p != 0;
}
__device__ __forceinline__ uint64_t mkdesc(uint32_t addr) {
    return ((uint64_t)2 << 61) | ((uint64_t)1 << 46) | ((uint64_t)64 << 32)
         | ((uint64_t)1 << 16) | ((addr >> 4) & 0x3FFF);
}
// SS form: A from SMEM desc
__device__ __forceinline__ void mma_ss(uint32_t d, uint64_t a, uint64_t b, uint32_t idesc, bool acc) {
    uint32_t en = acc ? 1u : 0u;
    asm volatile(
        "{\n\t.reg .pred p;\n\tsetp.ne.u32 p, %5, 0;\n\t"
        "tcgen05.mma.cta_group::1.kind::f16 [%0], %1, %2, %3, {%4,%4,%4,%4}, p;\n\t}"
        :: "r"(d), "l"(a), "l"(b), "r"(idesc), "r"(0u), "r"(en) : "memory");
}
// TS form: A from TMEM
__device__ __forceinline__ void mma_ts(uint32_t d, uint32_t a, uint64_t b, uint32_t idesc, bool acc) {
    uint32_t en = acc ? 1u : 0u;
    asm volatile(
        "{\n\t.reg .pred p;\n\tsetp.ne.u32 p, %5, 0;\n\t"
        "tcgen05.mma.cta_group::1.kind::f16 [%0], [%1], %2, %3, {%4,%4,%4,%4}, p;\n\t}"
        :: "r"(d), "r"(a), "l"(b), "r"(idesc), "r"(0u), "r"(en) : "memory");
}
#define TC_COMMIT(mbar) \
    asm volatile("tcgen05.commit.cta_group::1.mbarrier::arrive::one.shared::cluster.b64 [%0];" :: "r"(mbar) : "memory")
#define TC_ALLOC(smem_addr, n) \
    asm volatile("tcgen05.alloc.cta_group::1.sync.aligned.shared::cta.b32 [%0], %1;" :: "r"(smem_addr), "r"(n) : "memory")
#define TC_DEALLOC(tmem, n) \
    asm volatile("tcgen05.dealloc.cta_group::1.sync.aligned.b32 %0, %1;" :: "r"(tmem), "r"(n))
#define TC_RELINQ() asm volatile("tcgen05.relinquish_alloc_permit.cta_group::1.sync.aligned;")
#define TC_WAIT_LD() asm volatile("tcgen05.wait::ld.sync.aligned;" ::: "memory")
#define TC_WAIT_ST() asm volatile("tcgen05.wait::st.sync.aligned;" ::: "memory")
#define TC_FENCE_AFTER() asm volatile("tcgen05.fence::after_thread_sync;" ::: "memory")
#define TC_FENCE_BEFORE() asm volatile("tcgen05.fence::before_thread_sync;" ::: "memory")
#define FENCE_ASYNC() asm volatile("fence.proxy.async.shared::cta;" ::: "memory")
#define MB_INIT(addr, cnt) \
    asm volatile("mbarrier.init.shared.b64 [%0], %1;" :: "r"(addr), "r"(cnt) : "memory")

__device__ __forceinline__ void mb_wait(uint32_t mbar, uint32_t parity) {
    uint32_t done;
    asm volatile(
        "{\n\t.reg .pred p;\n\t"
        "mbarrier.try_wait.parity.acquire.cta.shared::cta.b64 p, [%1], %2;\n\t"
        "selp.b32 %0, 1, 0, p;\n\t}"
        : "=r"(done) : "r"(mbar), "r"(parity) : "memory");
    if (!done) {
        asm volatile(
            "{\n\t.reg .pred P1;\n\t"
            "WL_%=:\n\t"
            "mbarrier.try_wait.parity.acquire.cta.shared::cta.b64 P1, [%0], %1, 0x989680;\n\t"
            "@P1 bra.uni WD_%=;\n\t"
            "bra.uni WL_%=;\n\t"
            "WD_%=:\n\t}"
            :: "r"(mbar), "r"(parity) : "memory");
    }
}

#define LDTM_X32(r, addr) \
    asm volatile( \
        "tcgen05.ld.sync.aligned.32x32b.x32.b32 " \
        "{%0,%1,%2,%3,%4,%5,%6,%7,%8,%9,%10,%11,%12,%13,%14,%15," \
        "%16,%17,%18,%19,%20,%21,%22,%23,%24,%25,%26,%27,%28,%29,%30,%31}, [%32];" \
        : "=r"((r)[0]),"=r"((r)[1]),"=r"((r)[2]),"=r"((r)[3]),"=r"((r)[4]),"=r"((r)[5]), \
          "=r"((r)[6]),"=r"((r)[7]),"=r"((r)[8]),"=r"((r)[9]),"=r"((r)[10]),"=r"((r)[11]), \
          "=r"((r)[12]),"=r"((r)[13]),"=r"((r)[14]),"=r"((r)[15]),"=r"((r)[16]),"=r"((r)[17]), \
          "=r"((r)[18]),"=r"((r)[19]),"=r"((r)[20]),"=r"((r)[21]),"=r"((r)[22]),"=r"((r)[23]), \
          "=r"((r)[24]),"=r"((r)[25]),"=r"((r)[26]),"=r"((r)[27]),"=r"((r)[28]),"=r"((r)[29]), \
          "=r"((r)[30]),"=r"((r)[31]) : "r"(addr))

#define STTM_X32(addr, r) \
    asm volatile( \
        "tcgen05.st.sync.aligned.32x32b.x32.b32 [%0], " \
        "{%1,%2,%3,%4,%5,%6,%7,%8,%9,%10,%11,%12,%13,%14,%15,%16," \
        "%17,%18,%19,%20,%21,%22,%23,%24,%25,%26,%27,%28,%29,%30,%31,%32};" \
        :: "r"(addr), \
           "r"((r)[0]),"r"((r)[1]),"r"((r)[2]),"r"((r)[3]),"r"((r)[4]),"r"((r)[5]), \
           "r"((r)[6]),"r"((r)[7]),"r"((r)[8]),"r"((r)[9]),"r"((r)[10]),"r"((r)[11]), \
           "r"((r)[12]),"r"((r)[13]),"r"((r)[14]),"r"((r)[15]),"r"((r)[16]),"r"((r)[17]), \
           "r"((r)[18]),"r"((r)[19]),"r"((r)[20]),"r"((r)[21]),"r"((r)[22]),"r"((r)[23]), \
           "r"((r)[24]),"r"((r)[25]),"r"((r)[26]),"r"((r)[27]),"r"((r)[28]),"r"((r)[29]), \
           "r"((r)[30]),"r"((r)[31]) : "memory")
#endif  // __CUDA_ARCH_FEAT_SM103_ALL

// ---------------- projection GEMM (fp32 FFMA) ----------------
// mode 0: fp32 out. mode 1: Q (rope+QSCALE, split). mode 2: K (rope, split).
// mode 3: V (split, TRANSPOSED [b][h][d][key] output).
__global__ void __launch_bounds__(256) gemm_kernel(
    const float* __restrict__ A, const float* __restrict__ W,
    const float* __restrict__ bias, float* __restrict__ Cf,
    __nv_bfloat16* __restrict__ Oh, __nv_bfloat16* __restrict__ Ol,
    int mode, const float* __restrict__ fimg, const float* __restrict__ ftxt)
{
    __shared__ float As[32][68];
    __shared__ float Ws[32][68];
    const int m0 = blockIdx.x * 64;
    const int j0 = blockIdx.y * 64;
    const int tid = threadIdx.x;
    const int ty = tid >> 4, tx = tid & 15;

    float acc[4][4] = {};

    for (int k0 = 0; k0 < 256; k0 += 32) {
        #pragma unroll
        for (int l = 0; l < 2; l++) {
            int f = tid + l * 256;
            int r = f >> 3;
            int c = (f & 7) << 2;
            float4 va = make_float4(0.f, 0.f, 0.f, 0.f);
            int m = m0 + r;
            if (m < MROWS) va = *(const float4*)(A + (size_t)m * 256 + k0 + c);
            As[c + 0][r] = va.x; As[c + 1][r] = va.y;
            As[c + 2][r] = va.z; As[c + 3][r] = va.w;
            float4 vw = *(const float4*)(W + (size_t)(j0 + r) * 256 + k0 + c);
            Ws[c + 0][r] = vw.x; Ws[c + 1][r] = vw.y;
            Ws[c + 2][r] = vw.z; Ws[c + 3][r] = vw.w;
        }
        __syncthreads();
        #pragma unroll
        for (int kk = 0; kk < 32; kk++) {
            float a0[4], b0[4];
            *(float4*)a0 = *(const float4*)&As[kk][ty << 2];
            *(float4*)b0 = *(const float4*)&Ws[kk][tx << 2];
            #pragma unroll
            for (int i = 0; i < 4; i++)
                #pragma unroll
                for (int j = 0; j < 4; j++)
                    acc[i][j] += a0[i] * b0[j];
        }
        __syncthreads();
    }

    #pragma unroll
    for (int i = 0; i < 4; i++) {
        int m = m0 + (ty << 2) + i;
        if (m >= MROWS) break;
        int b = (m >= NN) ? 1 : 0;
        int n = m - b * NN;
        int jb = j0 + (tx << 2);
        float out[4];
        #pragma unroll
        for (int j = 0; j < 4; j++) out[j] = acc[i][j] + bias[jb + j];
        if (mode == 1 || mode == 2) {
            #pragma unroll
            for (int p = 0; p < 2; p++) {
                int j = jb + 2 * p;
                int cidx = (j & 31) >> 1;
                const float* f = (n < NIMG_)
                    ? (fimg + ((size_t)n * 16 + cidx) * 2)
                    : (ftxt + ((size_t)(n - NIMG_) * 16 + cidx) * 2);
                float cs = f[0], sn = f[1];
                float x0 = out[2 * p], x1 = out[2 * p + 1];
                out[2 * p]     = x0 * cs - x1 * sn;
                out[2 * p + 1] = x0 * sn + x1 * cs;
            }
        }
        if (mode == 1) {
            #pragma unroll
            for (int j = 0; j < 4; j++) out[j] *= QSCALE;
        }
        if (mode == 0) {
            *(float4*)(Cf + (size_t)m * 256 + jb) = *(float4*)out;
        } else if (mode == 3) {
            int head = jb >> 5;
            #pragma unroll
            for (int j = 0; j < 4; j++) {
                int d = (jb + j) & 31;
                size_t dst = ((size_t)(b * H_ + head) * HD_ + d) * NN + n;
                __nv_bfloat16 hb = __float2bfloat16(out[j]);
                float rr = out[j] - __bfloat162float(hb);
                Oh[dst] = hb;
                Ol[dst] = __float2bfloat16(rr);
            }
        } else {
            int head = jb >> 5;
            int col = jb & 31;
            size_t dst = ((size_t)(b * H_ + head) * NN + n) * HD_ + col;
            ushort hs[4], ls[4];
            #pragma unroll
            for (int j = 0; j < 4; j++) {
                __nv_bfloat16 hb = __float2bfloat16(out[j]);
                float rr = out[j] - __bfloat162float(hb);
                __nv_bfloat16 lb = __float2bfloat16(rr);
                hs[j] = __bfloat16_as_ushort(hb);
                ls[j] = __bfloat16_as_ushort(lb);
            }
            uint2 hp, lp;
            hp.x = (uint32_t)hs[0] | ((uint32_t)hs[1] << 16);
            hp.y = (uint32_t)hs[2] | ((uint32_t)hs[3] << 16);
            lp.x = (uint32_t)ls[0] | ((uint32_t)ls[1] << 16);
            lp.y = (uint32_t)ls[2] | ((uint32_t)ls[3] << 16);
            *(uint2*)(Oh + dst) = hp;
            *(uint2*)(Ol + dst) = lp;
        }
    }
}

#if defined(__CUDA_ARCH_FEAT_SM103_ALL)
// ---------------- attention loaders (tcgen05 path) ----------------
// K packed hi|lo tile: 128 rows x 128B (hi 0-63, lo 64-127), SW128.
__device__ __forceinline__ void load_rows_packed(
    char* dst, const __nv_bfloat16* gh, const __nv_bfloat16* gl,
    int valid, int tid)
{
    #pragma unroll
    for (int it = 0; it < 2; it++) {
        int f = tid + it * 256;      // 0..511
        int r = f >> 2;              // row 0..127
        int cb = (f & 3) * 16;       // byte col 0..48
        uint4 xh = make_uint4(0, 0, 0, 0), xl = make_uint4(0, 0, 0, 0);
        if (r < valid) {
            xh = *(const uint4*)((const char*)gh + (size_t)r * 64 + cb);
            xl = *(const uint4*)((const char*)gl + (size_t)r * 64 + cb);
        }
        *(uint4*)(dst + swz((uint32_t)(r * 128 + cb))) = xh;
        *(uint4*)(dst + swz((uint32_t)(r * 128 + 64 + cb))) = xl;
    }
}

// Vt tile from pre-transposed global: 32 d-rows x 128 keys, blocked SW128 atoms.
__device__ __forceinline__ void load_vt(
    char* dst, const __nv_bfloat16* gvh_t, const __nv_bfloat16* gvl_t,
    int valid, int tid)
{
    #pragma unroll
    for (int it = 0; it < 2; it++) {
        int c = tid + it * 256;      // 0..511
        int d = c >> 4;              // 0..31
        int kc = c & 15;             // 16-byte chunk (8 keys)
        uint4 xh = make_uint4(0, 0, 0, 0), xl = make_uint4(0, 0, 0, 0);
        if (kc * 8 < valid) {
            xh = *(const uint4*)(gvh_t + (size_t)d * NN + kc * 8);
            xl = *(const uint4*)(gvl_t + (size_t)d * NN + kc * 8);
        }
        uint32_t off = swz((uint32_t)((d >> 3) * 1024 + (kc >> 3) * 4096
                                      + (d & 7) * 128 + (kc & 7) * 16));
        *(uint4*)(dst + off) = xh;
        *(uint4*)(dst + 8192 + off) = xl;
    }
}

__device__ __forceinline__ void load_kv(
    char* smem, int buf,
    const __nv_bfloat16* kh, const __nv_bfloat16* kl,
    const __nv_bfloat16* vh_t, const __nv_bfloat16* vl_t,
    size_t khoff, size_t vtoff, int kbase, int valid, int tid)
{
    char* kb = smem + SM_KV0 + buf * KV_STRIDE;
    load_rows_packed(kb, kh + khoff + (size_t)kbase * 32,
                     kl + khoff + (size_t)kbase * 32, valid, tid);
    load_vt(kb + KV_VOFF, vh_t + vtoff + kbase, vl_t + vtoff + kbase, valid, tid);
}

// QK (TS): S = Qh.Kh + Qh.Kl + Ql.Kh
// Q TMEM: hi k-steps @+0,+8; lo @+16,+24. K desc: hi +0,+2; lo +4,+6.
__device__ __forceinline__ void issue_qk_ts(uint32_t tq, uint32_t kb, uint32_t tmem_d) {
    uint64_t kd = mkdesc(kb);
    mma_ts(tmem_d, tq + 0,  kd + 0, IDESC_QK, false);
    mma_ts(tmem_d, tq + 8,  kd + 2, IDESC_QK, true);
    mma_ts(tmem_d, tq + 0,  kd + 4, IDESC_QK, true);
    mma_ts(tmem_d, tq + 8,  kd + 6, IDESC_QK, true);
    mma_ts(tmem_d, tq + 16, kd + 0, IDESC_QK, true);
    mma_ts(tmem_d, tq + 24, kd + 2, IDESC_QK, true);
}

__device__ __forceinline__ void issue_pv(uint32_t phb, uint32_t vb, uint32_t tmem_d, bool first) {
    uint64_t aph = mkdesc(phb);
    uint64_t apl = mkdesc(phb + P_LOFF);
    uint64_t bvh = mkdesc(vb);
    uint64_t bvl = mkdesc(vb + 8192);
    #pragma unroll
    for (int term = 0; term < 3; term++) {
        uint64_t Aa = (term == 2) ? apl : aph;
        uint64_t Bb = (term == 1) ? bvl : bvh;
        #pragma unroll
        for (int ks = 0; ks < 8; ks++) {
            uint64_t ad = Aa + (ks < 4 ? 2 * ks : 1024 + 2 * (ks - 4));
            uint64_t bd = Bb + (ks < 4 ? 2 * ks : 256 + 2 * (ks - 4));
            mma_ss(tmem_d, ad, bd, IDESC_PV, !(first && term == 0 && ks == 0));
        }
    }
}

// Softmax epilogue: exp, accumulate l, write hi/lo bf16 P to SMEM (pbase buffer).
__device__ __forceinline__ void epilogue_tile(
    char* smem, uint32_t pbase, uint32_t tmem_s, int row, int half, int valid, float& lacc)
{
    const uint32_t xorc = (uint32_t)((row & 7) << 4);
    const uint32_t base0 = (uint32_t)((row >> 3) * 1024 + (row & 7) * 128);
    #pragma unroll
    for (int cc = 0; cc < 2; cc++) {
        const int c0 = half * 64 + cc * 32;
        uint32_t sreg[32];
        LDTM_X32(sreg, tmem_s + c0);
        TC_WAIT_LD();
        const uint32_t cbase = base0 + (uint32_t)((c0 >> 6) * 16384);
        const uint32_t kk0 = (uint32_t)((c0 & 63) * 2);
        if (valid >= c0 + 32) {
            #pragma unroll
            for (int j = 0; j < 32; j += 2) {
                float e0 = ex2f(__uint_as_float(sreg[j]));
                float e1 = ex2f(__uint_as_float(sreg[j + 1]));
                lacc += e0 + e1;
                uint32_t hp;
                asm("cvt.rn.bf16x2.f32 %0, %1, %2;" : "=r"(hp) : "f"(e1), "f"(e0));
                float h0 = __uint_as_float(hp << 16);
                float h1 = __uint_as_float(hp & 0xFFFF0000u);
                uint32_t lp;
                asm("cvt.rn.bf16x2.f32 %0, %1, %2;" : "=r"(lp) : "f"(e1 - h1), "f"(e0 - h0));
                uint32_t off = cbase + ((kk0 + 2 * j) ^ xorc);
                *(uint32_t*)(smem + pbase + off) = hp;
                *(uint32_t*)(smem + pbase + P_LOFF + off) = lp;
            }
        } else {
            #pragma unroll
            for (int j = 0; j < 32; j += 2) {
                int col = c0 + j;
                float e0 = (col < valid)     ? ex2f(__uint_as_float(sreg[j]))     : 0.f;
                float e1 = (col + 1 < valid) ? ex2f(__uint_as_float(sreg[j + 1])) : 0.f;
                lacc += e0 + e1;
                uint32_t hp;
                asm("cvt.rn.bf16x2.f32 %0, %1, %2;" : "=r"(hp) : "f"(e1), "f"(e0));
                float h0 = __uint_as_float(hp << 16);
                float h1 = __uint_as_float(hp & 0xFFFF0000u);
                uint32_t lp;
                asm("cvt.rn.bf16x2.f32 %0, %1, %2;" : "=r"(lp) : "f"(e1 - h1), "f"(e0 - h0));
                uint32_t off = cbase + ((kk0 + 2 * j) ^ xorc);
                *(uint32_t*)(smem + pbase + off) = hp;
                *(uint32_t*)(smem + pbase + P_LOFF + off) = lp;
            }
        }
    }
}
#endif  // __CUDA_ARCH_FEAT_SM103_ALL

// ---------------- attention kernel ----------------
__global__ void __launch_bounds__(256, 1) attn_kernel(
    const __nv_bfloat16* __restrict__ qh, const __nv_bfloat16* __restrict__ ql,
    const __nv_bfloat16* __restrict__ kh, const __nv_bfloat16* __restrict__ kl,
    const __nv_bfloat16* __restrict__ vh_t, const __nv_bfloat16* __restrict__ vl_t,
    float* __restrict__ ao)
{
    extern __shared__ __align__(1024) char smem[];
    const int tid = threadIdx.x;
    const int b = blockIdx.z, h = blockIdx.y;
    const size_t khoff = (size_t)(b * H_ + h) * NN * HD_;   // Q/K layout
    const size_t vtoff = (size_t)(b * H_ + h) * HD_ * NN;   // Vt layout
    const int q0 = blockIdx.x * 128;
    const int qvalid = min(128, NN - q0);

#if defined(__CUDA_ARCH_FEAT_SM103_ALL)
    const uint32_t sbase = smem_u32(smem);
    const int wid = tid >> 5;
    const int lane = tid & 31;
    const int half = wid >> 2;
    const int row = (wid & 3) * 32 + lane;

    if (wid == 0) TC_ALLOC(sbase + SM_TM, 512);
    if (tid == 0) { MB_INIT(sbase + SM_MBS, 1); MB_INIT(sbase + SM_MBO, 1); }
    __syncthreads();
    uint32_t tmem;
    asm volatile("ld.shared.b32 %0, [%1];" : "=r"(tmem) : "r"(sbase + SM_TM));

    // prologue: Q -> TMEM (warps 0-3), KV tiles 0 and 1 -> SMEM
    if (wid < 4) {
        uint32_t a[32];
        int r = wid * 32 + lane;
        if (r < qvalid) {
            const uint4* ph = (const uint4*)(qh + khoff + (size_t)(q0 + r) * 32);
            const uint4* pl = (const uint4*)(ql + khoff + (size_t)(q0 + r) * 32);
            #pragma unroll
            for (int i = 0; i < 4; i++) {
                uint4 x = ph[i];
                a[4 * i + 0] = x.x; a[4 * i + 1] = x.y;
                a[4 * i + 2] = x.z; a[4 * i + 3] = x.w;
                uint4 y = pl[i];
                a[16 + 4 * i + 0] = y.x; a[16 + 4 * i + 1] = y.y;
                a[16 + 4 * i + 2] = y.z; a[16 + 4 * i + 3] = y.w;
            }
        } else {
            #pragma unroll
            for (int i = 0; i < 32; i++) a[i] = 0;
        }
        uint32_t woff = (uint32_t)wid << 21;
        STTM_X32(tmem + TM_Q + woff, a);
        TC_WAIT_ST();
        TC_FENCE_BEFORE();
    }
    load_kv(smem, 0, kh, kl, vh_t, vl_t, khoff, vtoff, 0, 128, tid);
    load_kv(smem, 1, kh, kl, vh_t, vl_t, khoff, vtoff, 128, 128, tid);
    FENCE_ASYNC();
    __syncthreads();
    if (wid == 0 && elect1()) {
        TC_FENCE_AFTER();
        issue_qk_ts(tmem + TM_Q, sbase + SM_KV0, tmem + TM_S0);
        TC_COMMIT(sbase + SM_MBS);
    }

    uint32_t pS = 0, pO = 0;
    float lacc1 = 0.f, lacc2 = 0.f;

    for (int t = 0; t < NTALL; t++) {
        const int valid = (t < NT1) ? min(128, NKD - t * 128) : NKE_;
        // S(t) ready (QK(t) issued a full tile ago)
        mb_wait(sbase + SM_MBS, pS); pS ^= 1;
        TC_FENCE_AFTER();
        // issue QK(t+1): K(t+1) loaded during t-1; S[(t+1)&1] freed by epilogue(t-1)
        if (t + 1 < NTALL && wid == 0 && elect1()) {
            issue_qk_ts(tmem + TM_Q, sbase + SM_KV0 + ((t + 1) % 3) * KV_STRIDE,
                        tmem + (((t + 1) & 1) ? TM_S1 : TM_S0));
            TC_COMMIT(sbase + SM_MBS);
        }
        // V-buffer reuse: PV(t-1) must be done before overwriting buf (t+2)%3
        if (t >= 1) { mb_wait(sbase + SM_MBO, pO); pO ^= 1; }
        // KV(t+2) loads — LDG latency hides under the epilogue
        if (t + 2 < NTALL) {
            int nb = (t + 2 < NT1) ? (t + 2) * 128 : NKD;
            int nv = (t + 2 < NT1) ? min(128, NKD - nb) : NKE_;
            load_kv(smem, (t + 2) % 3, kh, kl, vh_t, vl_t, khoff, vtoff, nb, nv, tid);
        }
        // softmax epilogue: S[t&1] -> P[t&1]  (PV(t-1) reads P[(t-1)&1] concurrently)
        epilogue_tile(smem, (t & 1) ? SM_P1 : SM_P0,
                      tmem + ((t & 1) ? TM_S1 : TM_S0), row, half, valid,
                      (t < NT1) ? lacc1 : lacc2);
        TC_FENCE_BEFORE();
        FENCE_ASYNC();
        __syncthreads();
        if (wid == 0 && elect1()) {
            issue_pv(sbase + ((t & 1) ? SM_P1 : SM_P0),
                     sbase + SM_KV0 + (t % 3) * KV_STRIDE + KV_VOFF,
                     tmem + ((t < NT1) ? TM_O1 : TM_O2),
                     (t == 0) || (t == NT1));
            TC_COMMIT(sbase + SM_MBO);
        }
    }

    // combine l across warp halves
    float* lsum1 = (float*)(smem + SM_LSUM1);
    float* lsum2 = (float*)(smem + SM_LSUM2);
    if (half == 1) { lsum1[row] = lacc1; lsum2[row] = lacc2; }
    __syncthreads();

    mb_wait(sbase + SM_MBO, pO); pO ^= 1;   // final PV done => O1, O2 final
    TC_FENCE_AFTER();
    if (half == 0) {
        float l1 = lacc1 + lsum1[row];
        float l2 = lacc2 + lsum2[row];
        uint32_t o1[32], o2[32];
        LDTM_X32(o1, tmem + TM_O1);
        LDTM_X32(o2, tmem + TM_O2);
        TC_WAIT_LD();
        float inv1 = 1.f / l1, inv2 = 1.f / l2;
        if (row < qvalid) {
            float* orow = ao + ((size_t)(b * NN + q0 + row)) * 256 + h * 32;
            #pragma unroll
            for (int d = 0; d < 32; d += 4) {
                float4 tv;
                tv.x = __uint_as_float(o1[d])     * inv1 + __uint_as_float(o2[d])     * inv2;
                tv.y = __uint_as_float(o1[d + 1]) * inv1 + __uint_as_float(o2[d + 1]) * inv2;
                tv.z = __uint_as_float(o1[d + 2]) * inv1 + __uint_as_float(o2[d + 2]) * inv2;
                tv.w = __uint_as_float(o1[d + 3]) * inv1 + __uint_as_float(o2[d + 3]) * inv2;
                *(float4*)(orow + d) = tv;
            }
        }
    }
    __syncthreads();
    if (wid == 0) {
        TC_RELINQ();
        TC_DEALLOC(tmem, 512);
    }
#else
    // -------- scalar fallback (runs only if the sm_103a cubin is absent) ----
    const int qi = q0 + (tid & 127);
    const int hsel = tid >> 7;
    const bool active = qi < NN;

    float q[HD_];
    if (active) {
        #pragma unroll
        for (int d = 0; d < HD_; d++) {
            size_t idx = khoff + (size_t)qi * HD_ + d;
            q[d] = __bfloat162float(qh[idx]) + __bfloat162float(ql[idx]);
        }
    } else {
        #pragma unroll
        for (int d = 0; d < HD_; d++) q[d] = 0.f;
    }

    float o1[HD_] = {}, o2[HD_] = {};
    float l1 = 0.f, l2 = 0.f;
    const int ks = hsel ? 2048 : 0;
    const int ke = hsel ? NKD : 2048;
    if (active) {
        for (int j = ks; j < ke; j++) {
            size_t base = khoff + (size_t)j * HD_;
            float s = 0.f;
            #pragma unroll
            for (int d = 0; d < HD_; d++)
                s += q[d] * (__bfloat162float(kh[base + d]) + __bfloat162float(kl[base + d]));
            float e = ex2f(s);
            l1 += e;
            #pragma unroll
            for (int d = 0; d < HD_; d++) {
                size_t vi = vtoff + (size_t)d * NN + j;
                o1[d] += e * (__bfloat162float(vh_t[vi]) + __bfloat162float(vl_t[vi]));
            }
        }
        if (hsel == 1) {
            for (int j = NKD; j < NN; j++) {
                size_t base = khoff + (size_t)j * HD_;
                float s = 0.f;
                #pragma unroll
                for (int d = 0; d < HD_; d++)
                    s += q[d] * (__bfloat162float(kh[base + d]) + __bfloat162float(kl[base + d]));
                float e = ex2f(s);
                l2 += e;
                #pragma unroll
                for (int d = 0; d < HD_; d++) {
                    size_t vi = vtoff + (size_t)d * NN + j;
                    o2[d] += e * (__bfloat162float(vh_t[vi]) + __bfloat162float(vl_t[vi]));
                }
            }
        }
    }
    float* sh = (float*)smem;
    float* shl = sh + 128 * HD_;
    float* sh2 = shl + 128;
    float* sh2l = sh2 + 128 * HD_;
    if (hsel == 1) {
        int r = tid & 127;
        #pragma unroll
        for (int d = 0; d < HD_; d++) { sh[r * HD_ + d] = o1[d]; sh2[r * HD_ + d] = o2[d]; }
        shl[r] = l1; sh2l[r] = l2;
    }
    __syncthreads();
    if (hsel == 0 && active) {
        int r = tid & 127;
        float lt = l1 + shl[r];
        float inv1 = 1.f / lt;
        float inv2 = 1.f / sh2l[r];
        float* orow = ao + ((size_t)(b * NN + qi)) * 256 + h * HD_;
        #pragma unroll
        for (int d = 0; d < HD_; d++)
            orow[d] = (o1[d] + sh[r * HD_ + d]) * inv1 + sh2[r * HD_ + d] * inv2;
    }
#endif
}

// ---------------- launch ----------------
extern "C" void kernel_launch(void* const* d_in, const int* in_sizes, int n_in,
                              void* d_out, int out_size)
{
    const float* q    = (const float*)d_in[0];
    const float* k    = (const float*)d_in[1];
    const float* v    = (const float*)d_in[2];
    const float* fimg = (const float*)d_in[3];
    const float* ftxt = (const float*)d_in[4];
    const float* Wq   = (const float*)d_in[5];
    const float* bq   = (const float*)d_in[6];
    const float* Wk   = (const float*)d_in[7];
    const float* bk   = (const float*)d_in[8];
    const float* Wv   = (const float*)d_in[9];
    const float* bv   = (const float*)d_in[10];
    const float* Wo   = (const float*)d_in[11];
    const float* bo   = (const float*)d_in[12];
    float* out = (float*)d_out;

    __nv_bfloat16 *qh, *ql, *kh, *kl, *vh, *vl;
    float* ao;
    cudaGetSymbolAddress((void**)&qh, g_qh);
    cudaGetSymbolAddress((void**)&ql, g_ql);
    cudaGetSymbolAddress((void**)&kh, g_kh);
    cudaGetSymbolAddress((void**)&kl, g_kl);
    cudaGetSymbolAddress((void**)&vh, g_vh);
    cudaGetSymbolAddress((void**)&vl, g_vl);
    cudaGetSymbolAddress((void**)&ao, g_ao);

    cudaFuncSetAttribute(attn_kernel, cudaFuncAttributeMaxDynamicSharedMemorySize, SMEM_TOTAL);

    dim3 gg(129, 4, 1);
    gemm_kernel<<<gg, 256>>>(q, Wq, bq, nullptr, qh, ql, 1, fimg, ftxt);
    gemm_kernel<<<gg, 256>>>(k, Wk, bk, nullptr, kh, kl, 2, fimg, ftxt);
    gemm_kernel<<<gg, 256>>>(v, Wv, bv, nullptr, vh, vl, 3, nullptr, nullptr);

    dim3 ga(33, H_, BB);
    attn_kernel<<<ga, 256, SMEM_TOTAL>>>(qh, ql, kh, kl, vh, vl, ao);

    gemm_kernel<<<gg, 256>>>(ao, Wo, bo, out, nullptr, nullptr, 0, nullptr, nullptr);
}

// round 8
// speedup vs baseline: 1.7766x; 1.7766x over previous
#include <cuda_runtime.h>
#include <cuda_bf16.h>
#include <stdint.h>
#include <math.h>

#define D_    256
#define H_    8
#define HD_   32
#define NIMG_ 4096
#define NN    4112
#define BB    2
#define NKE_  64
#define MROWS (BB * NN)      /* 8224 */
#define NKD   (NN - NKE_)    /* 4048 */
#define NT1   32             /* ceil(4048/128) */
#define NTALL 33             /* 32 dense tiles + 1 mem tile */
#define MT    65             /* ceil(8224/128) GEMM row tiles */

// ---------------- global scratch (no allocs allowed) ----------------
// Q/K packed: per (b,h,n) one 128B row: hi bf16 d0..31 at [0,64), lo at [64,128)
__device__ uint8_t g_q[(size_t)BB * H_ * NN * 128];
__device__ uint8_t g_k[(size_t)BB * H_ * NN * 128];
// V transposed: [b][h][d][key], hi and lo arrays
__device__ __nv_bfloat16 g_vh[(size_t)BB * H_ * HD_ * NN];
__device__ __nv_bfloat16 g_vl[(size_t)BB * H_ * HD_ * NN];
__device__ float g_ao[(size_t)MROWS * D_];

// scale: 1/sqrt(32) * log2(e)  (so softmax exp == exp2)
#define QSCALE (0.17677669529663687f * 1.4426950408889634f)

// idesc kind::f16: dtypeF32(1<<4) | aBF16(1<<7) | bBF16(1<<10) | (N/8)<<17 | (M/16)<<24
#define IDESC_128 0x8200490u  /* M=128 N=128 */
#define IDESC_PV  0x8080490u  /* M=128 N=32  */

// ---------------- arch-portable helpers ----------------
__device__ __forceinline__ uint32_t smem_u32(const void* p) {
    uint32_t a;
    asm("{ .reg .u64 t; cvta.to.shared.u64 t, %1; cvt.u32.u64 %0, t; }" : "=r"(a) : "l"(p));
    return a;
}
__device__ __forceinline__ float ex2f(float x) {
    float y; asm("ex2.approx.ftz.f32 %0, %1;" : "=f"(y) : "f"(x)); return y;
}
__device__ __forceinline__ uint32_t swz(uint32_t b) { return b ^ ((b >> 3) & 0x70); }
// pack two floats to bf16x2: 'lo' in low 16 bits
__device__ __forceinline__ uint32_t pack_bf(float hi, float lo) {
    uint32_t r; asm("cvt.rn.bf16x2.f32 %0, %1, %2;" : "=r"(r) : "f"(hi), "f"(lo)); return r;
}

// ---------------- tcgen05 helpers: sm_103a ONLY ----------------
#if defined(__CUDA_ARCH_FEAT_SM103_ALL)
__device__ __forceinline__ bool elect1() {
    uint32_t p;
    asm volatile("{ .reg .pred p; elect.sync _|p, 0xFFFFFFFF; selp.b32 %0, 1, 0, p; }" : "=r"(p));
    return p != 0;
}
__device__ __forceinline__ uint64_t mkdesc(uint32_t addr) {
    return ((uint64_t)2 << 61) | ((uint64_t)1 << 46) | ((uint64_t)64 << 32)
         | ((uint64_t)1 << 16) | ((addr >> 4) & 0x3FFF);
}
__device__ __forceinline__ void mma_ss(uint32_t d, uint64_t a, uint64_t b, uint32_t idesc, bool acc) {
    uint32_t en = acc ? 1u : 0u;
    asm volatile(
        "{\n\t.reg .pred p;\n\tsetp.ne.u32 p, %5, 0;\n\t"
        "tcgen05.mma.cta_group::1.kind::f16 [%0], %1, %2, %3, {%4,%4,%4,%4}, p;\n\t}"
        :: "r"(d), "l"(a), "l"(b), "r"(idesc), "r"(0u), "r"(en) : "memory");
}
#define TC_COMMIT(mbar) \
    asm volatile("tcgen05.commit.cta_group::1.mbarrier::arrive::one.shared::cluster.b64 [%0];" :: "r"(mbar) : "memory")
#define TC_ALLOC(smem_addr, n) \
    asm volatile("tcgen05.alloc.cta_group::1.sync.aligned.shared::cta.b32 [%0], %1;" :: "r"(smem_addr), "r"(n) : "memory")
#define TC_DEALLOC(tmem, n) \
    asm volatile("tcgen05.dealloc.cta_group::1.sync.aligned.b32 %0, %1;" :: "r"(tmem), "r"(n))
#define TC_RELINQ() asm volatile("tcgen05.relinquish_alloc_permit.cta_group::1.sync.aligned;")
#define TC_WAIT_LD() asm volatile("tcgen05.wait::ld.sync.aligned;" ::: "memory")
#define TC_FENCE_AFTER() asm volatile("tcgen05.fence::after_thread_sync;" ::: "memory")
#define TC_FENCE_BEFORE() asm volatile("tcgen05.fence::before_thread_sync;" ::: "memory")
#define FENCE_ASYNC() asm volatile("fence.proxy.async.shared::cta;" ::: "memory")
#define MB_INIT(addr, cnt) \
    asm volatile("mbarrier.init.shared.b64 [%0], %1;" :: "r"(addr), "r"(cnt) : "memory")

__device__ __forceinline__ void mb_wait(uint32_t mbar, uint32_t parity) {
    uint32_t done;
    asm volatile(
        "{\n\t.reg .pred p;\n\t"
        "mbarrier.try_wait.parity.acquire.cta.shared::cta.b64 p, [%1], %2;\n\t"
        "selp.b32 %0, 1, 0, p;\n\t}"
        : "=r"(done) : "r"(mbar), "r"(parity) : "memory");
    if (!done) {
        asm volatile(
            "{\n\t.reg .pred P1;\n\t"
            "WL_%=:\n\t"
            "mbarrier.try_wait.parity.acquire.cta.shared::cta.b64 P1, [%0], %1, 0x989680;\n\t"
            "@P1 bra.uni WD_%=;\n\t"
            "bra.uni WL_%=;\n\t"
            "WD_%=:\n\t}"
            :: "r"(mbar), "r"(parity) : "memory");
    }
}

#define LDTM_X32(r, addr) \
    asm volatile( \
        "tcgen05.ld.sync.aligned.32x32b.x32.b32 " \
        "{%0,%1,%2,%3,%4,%5,%6,%7,%8,%9,%10,%11,%12,%13,%14,%15," \
        "%16,%17,%18,%19,%20,%21,%22,%23,%24,%25,%26,%27,%28,%29,%30,%31}, [%32];" \
        : "=r"((r)[0]),"=r"((r)[1]),"=r"((r)[2]),"=r"((r)[3]),"=r"((r)[4]),"=r"((r)[5]), \
          "=r"((r)[6]),"=r"((r)[7]),"=r"((r)[8]),"=r"((r)[9]),"=r"((r)[10]),"=r"((r)[11]), \
          "=r"((r)[12]),"=r"((r)[13]),"=r"((r)[14]),"=r"((r)[15]),"=r"((r)[16]),"=r"((r)[17]), \
          "=r"((r)[18]),"=r"((r)[19]),"=r"((r)[20]),"=r"((r)[21]),"=r"((r)[22]),"=r"((r)[23]), \
          "=r"((r)[24]),"=r"((r)[25]),"=r"((r)[26]),"=r"((r)[27]),"=r"((r)[28]),"=r"((r)[29]), \
          "=r"((r)[30]),"=r"((r)[31]) : "r"(addr))
#endif  // __CUDA_ARCH_FEAT_SM103_ALL

// ================= tcgen05 projection GEMM =================
// C[m,j] = sum_i A[m,i]*W[j,i] + bias[j], M tile 128 per CTA, K=256 in 4 chunks of 64.
// 3-term bf16 hi/lo emulation. Epilogue by mode:
//  0: fp32 out (O projection)  1: Q (rope+QSCALE -> packed g_q)
//  2: K (rope -> packed g_k)   3: V (transposed g_vh/g_vl)
#define GS_AH   0        /* 16384 */
#define GS_AL   16384    /* 16384 */
#define GS_WH   32768    /* 32768 */
#define GS_WL   65536    /* 32768 */
#define GS_FREQ 98304    /* 16384: float2 [cidx 16][row 128] */
#define GS_BIAS 114688   /* 1024 */
#define GS_TM   115712
#define GS_MB   115720
#define GS_TOTAL 115840

__global__ void __launch_bounds__(256) gemm_tc(
    const float* __restrict__ A0, const float* __restrict__ A1, const float* __restrict__ A2,
    const float* __restrict__ W0, const float* __restrict__ W1, const float* __restrict__ W2,
    const float* __restrict__ B0, const float* __restrict__ B1, const float* __restrict__ B2,
    uint8_t* __restrict__ gq, uint8_t* __restrict__ gk,
    __nv_bfloat16* __restrict__ gvh, __nv_bfloat16* __restrict__ gvl,
    float* __restrict__ outf, int qkv,
    const float* __restrict__ fimg, const float* __restrict__ ftxt)
{
    extern __shared__ __align__(1024) char smem[];
    const int tid = threadIdx.x;
    const int m0 = blockIdx.x * 128;
    int mode;
    const float *A, *W, *bias;
    if (qkv) {
        mode = blockIdx.y + 1;
        if (blockIdx.y == 0)      { A = A0; W = W0; bias = B0; }
        else if (blockIdx.y == 1) { A = A1; W = W1; bias = B1; }
        else                      { A = A2; W = W2; bias = B2; }
    } else { mode = 0; A = A0; W = W0; bias = B0; }

#if defined(__CUDA_ARCH_FEAT_SM103_ALL)
    const uint32_t sb = smem_u32(smem);
    const int wid = tid >> 5;
    const int lane = tid & 31;

    if (wid == 0) TC_ALLOC(sb + GS_TM, 256);
    if (tid == 0) MB_INIT(sb + GS_MB, 1);
    __syncthreads();
    uint32_t tmem;
    asm volatile("ld.shared.b32 %0, [%1];" : "=r"(tmem) : "r"(sb + GS_TM));

    // stage bias
    if (tid < 256) *(float*)(smem + GS_BIAS + tid * 4) = bias[tid];
    // stage freqs (modes 1,2): sfreq[cidx][row] float2
    if (mode == 1 || mode == 2) {
        int r = tid >> 1;
        int hh = tid & 1;
        int m = m0 + r;
        #pragma unroll
        for (int cc = 0; cc < 8; cc++) {
            int cidx = hh * 8 + cc;
            float2 f = make_float2(1.f, 0.f);
            if (m < MROWS) {
                int bb = (m >= NN) ? 1 : 0;
                int n = m - bb * NN;
                f = (n < NIMG_) ? *(const float2*)(fimg + ((size_t)n * 16 + cidx) * 2)
                                : *(const float2*)(ftxt + ((size_t)(n - NIMG_) * 16 + cidx) * 2);
            }
            *(float2*)(smem + GS_FREQ + ((size_t)cidx * 128 + r) * 8) = f;
        }
    }

    uint32_t par = 0;
    for (int c = 0; c < 4; c++) {
        if (c > 0) { mb_wait(sb + GS_MB, par); par ^= 1; }
        const int k0 = c * 64;
        // load A chunk: 128 rows x 64 floats -> hi/lo bf16
        #pragma unroll
        for (int it = 0; it < 8; it++) {
            int i = tid + it * 256;          // 0..2047
            int r = i >> 4;
            int c4 = (i & 15) * 4;
            float4 va = make_float4(0.f, 0.f, 0.f, 0.f);
            if (m0 + r < MROWS) va = *(const float4*)(A + (size_t)(m0 + r) * 256 + k0 + c4);
            uint32_t h01 = pack_bf(va.y, va.x);
            uint32_t h23 = pack_bf(va.w, va.z);
            float hx = __uint_as_float(h01 << 16), hy = __uint_as_float(h01 & 0xFFFF0000u);
            float hz = __uint_as_float(h23 << 16), hw = __uint_as_float(h23 & 0xFFFF0000u);
            uint32_t l01 = pack_bf(va.y - hy, va.x - hx);
            uint32_t l23 = pack_bf(va.w - hw, va.z - hz);
            uint32_t off = swz((uint32_t)(r * 128 + c4 * 2));
            *(uint2*)(smem + GS_AH + off) = make_uint2(h01, h23);
            *(uint2*)(smem + GS_AL + off) = make_uint2(l01, l23);
        }
        // load W chunk: 256 rows x 64 floats
        #pragma unroll
        for (int it = 0; it < 16; it++) {
            int i = tid + it * 256;          // 0..4095
            int r = i >> 4;
            int c4 = (i & 15) * 4;
            float4 vw = *(const float4*)(W + (size_t)r * 256 + k0 + c4);
            uint32_t h01 = pack_bf(vw.y, vw.x);
            uint32_t h23 = pack_bf(vw.w, vw.z);
            float hx = __uint_as_float(h01 << 16), hy = __uint_as_float(h01 & 0xFFFF0000u);
            float hz = __uint_as_float(h23 << 16), hw = __uint_as_float(h23 & 0xFFFF0000u);
            uint32_t l01 = pack_bf(vw.y - hy, vw.x - hx);
            uint32_t l23 = pack_bf(vw.w - hw, vw.z - hz);
            uint32_t off = swz((uint32_t)(r * 128 + c4 * 2));
            *(uint2*)(smem + GS_WH + off) = make_uint2(h01, h23);
            *(uint2*)(smem + GS_WL + off) = make_uint2(l01, l23);
        }
        FENCE_ASYNC();
        __syncthreads();
        if (wid == 0 && elect1()) {
            uint64_t ah = mkdesc(sb + GS_AH), al = mkdesc(sb + GS_AL);
            uint64_t wh = mkdesc(sb + GS_WH), wl = mkdesc(sb + GS_WL);
            #pragma unroll
            for (int nh = 0; nh < 2; nh++) {
                uint32_t dcol = tmem + nh * 128;
                uint64_t bo = (uint64_t)nh * 1024;
                #pragma unroll
                for (int ks = 0; ks < 4; ks++) {
                    uint64_t a_h = ah + 2 * ks, a_l = al + 2 * ks;
                    uint64_t b_h = wh + bo + 2 * ks, b_l = wl + bo + 2 * ks;
                    mma_ss(dcol, a_h, b_h, IDESC_128, !(c == 0 && ks == 0));
                    mma_ss(dcol, a_h, b_l, IDESC_128, true);
                    mma_ss(dcol, a_l, b_h, IDESC_128, true);
                }
            }
            TC_COMMIT(sb + GS_MB);
        }
    }
    mb_wait(sb + GS_MB, par);
    TC_FENCE_AFTER();

    // epilogue: warp w -> rows (w&3)*32+lane, cols (w>>2)*128 + cc*32
    {
        const int r = (wid & 3) * 32 + lane;
        const int m = m0 + r;
        const int cb0 = (wid >> 2) * 128;
        const bool mok = (m < MROWS);
        int bb = (m >= NN) ? 1 : 0;
        int n = m - bb * NN;
        #pragma unroll
        for (int cc = 0; cc < 4; cc++) {
            const int c0 = cb0 + cc * 32;
            uint32_t s[32];
            LDTM_X32(s, tmem + c0);
            TC_WAIT_LD();
            if (!mok) continue;
            if (mode == 0) {
                #pragma unroll
                for (int j = 0; j < 32; j++) {
                    float bv = *(const float*)(smem + GS_BIAS + (c0 + j) * 4);
                    outf[(size_t)m * 256 + c0 + j] = __uint_as_float(s[j]) + bv;
                }
            } else if (mode == 3) {
                const int head = c0 >> 5;
                #pragma unroll
                for (int j = 0; j < 32; j++) {
                    float bv = *(const float*)(smem + GS_BIAS + (c0 + j) * 4);
                    float val = __uint_as_float(s[j]) + bv;
                    __nv_bfloat16 hb = __float2bfloat16(val);
                    float rr = val - __bfloat162float(hb);
                    size_t dst = ((size_t)(bb * H_ + head) * HD_ + j) * NN + n;
                    gvh[dst] = hb;
                    gvl[dst] = __float2bfloat16(rr);
                }
            } else {
                const int head = c0 >> 5;
                uint8_t* gout = (mode == 1) ? gq : gk;
                uint8_t* rowp = gout + ((size_t)(bb * H_ + head) * NN + n) * 128;
                #pragma unroll
                for (int p = 0; p < 16; p++) {
                    float b0v = *(const float*)(smem + GS_BIAS + (c0 + 2 * p) * 4);
                    float b1v = *(const float*)(smem + GS_BIAS + (c0 + 2 * p + 1) * 4);
                    float x0 = __uint_as_float(s[2 * p]) + b0v;
                    float x1 = __uint_as_float(s[2 * p + 1]) + b1v;
                    float2 f = *(const float2*)(smem + GS_FREQ + ((size_t)p * 128 + r) * 8);
                    float y0 = x0 * f.x - x1 * f.y;
                    float y1 = x0 * f.y + x1 * f.x;
                    if (mode == 1) { y0 *= QSCALE; y1 *= QSCALE; }
                    uint32_t hp = pack_bf(y1, y0);
                    float h0 = __uint_as_float(hp << 16);
                    float h1 = __uint_as_float(hp & 0xFFFF0000u);
                    uint32_t lp = pack_bf(y1 - h1, y0 - h0);
                    *(uint32_t*)(rowp + p * 4) = hp;
                    *(uint32_t*)(rowp + 64 + p * 4) = lp;
                }
            }
        }
    }
    __syncthreads();
    if (wid == 0) {
        TC_RELINQ();
        TC_DEALLOC(tmem, 256);
    }
#else
    // naive fallback (only if sm_103a cubin absent)
    for (int idx = tid; idx < 128 * 128; idx += 256) {
        int r = idx >> 7;
        int p = idx & 127;        // pair over 256 cols
        int m = m0 + r;
        if (m >= MROWS) continue;
        int j0_ = p * 2;
        float s0 = bias[j0_], s1 = bias[j0_ + 1];
        for (int k2 = 0; k2 < 256; k2++) {
            float a = A[(size_t)m * 256 + k2];
            s0 += a * W[(size_t)j0_ * 256 + k2];
            s1 += a * W[(size_t)(j0_ + 1) * 256 + k2];
        }
        int bb = (m >= NN) ? 1 : 0;
        int n = m - bb * NN;
        if (mode == 1 || mode == 2) {
            int cidx = (j0_ & 31) >> 1;
            const float* f = (n < NIMG_) ? (fimg + ((size_t)n * 16 + cidx) * 2)
                                         : (ftxt + ((size_t)(n - NIMG_) * 16 + cidx) * 2);
            float y0 = s0 * f[0] - s1 * f[1];
            float y1 = s0 * f[1] + s1 * f[0];
            if (mode == 1) { y0 *= QSCALE; y1 *= QSCALE; }
            int head = j0_ >> 5, d = j0_ & 31;
            uint8_t* gout = (mode == 1) ? gq : gk;
            uint8_t* rowp = gout + ((size_t)(bb * H_ + head) * NN + n) * 128;
            uint32_t hp = pack_bf(y1, y0);
            float h0 = __uint_as_float(hp << 16), h1 = __uint_as_float(hp & 0xFFFF0000u);
            uint32_t lp = pack_bf(y1 - h1, y0 - h0);
            *(uint32_t*)(rowp + (d >> 1) * 4) = hp;
            *(uint32_t*)(rowp + 64 + (d >> 1) * 4) = lp;
        } else if (mode == 3) {
            int head = j0_ >> 5, d = j0_ & 31;
            #pragma unroll
            for (int e = 0; e < 2; e++) {
                float val = e ? s1 : s0;
                __nv_bfloat16 hb = __float2bfloat16(val);
                size_t dst = ((size_t)(bb * H_ + head) * HD_ + d + e) * NN + n;
                gvh[dst] = hb;
                gvl[dst] = __float2bfloat16(val - __bfloat162float(hb));
            }
        } else {
            outf[(size_t)m * 256 + j0_] = s0;
            outf[(size_t)m * 256 + j0_ + 1] = s1;
        }
    }
#endif
}

// ================= attention (R5 structure, packed Q/K) =================
#define SM_Q     0          /* 16384: packed hi|lo rows */
#define SM_KV0   16384
#define KV_STRIDE 32768
#define KV_VOFF  16384
#define SM_PH    147456     /* 32KB */
#define SM_PL    180224     /* 32KB */
#define SM_TM    212992
#define SM_MBS   213000
#define SM_MBO   213008
#define SM_LSUM1 213056
#define SM_LSUM2 213568
#define SMEM_TOTAL 214080

#define TM_S0 0
#define TM_S1 128
#define TM_O1 256
#define TM_O2 288

#if defined(__CUDA_ARCH_FEAT_SM103_ALL)
// copy 128 packed 128B rows from global into SW128-swizzled SMEM
__device__ __forceinline__ void load_rows_packed(
    char* dst, const uint8_t* gpk, int valid, int tid)
{
    #pragma unroll
    for (int it = 0; it < 4; it++) {
        int f = tid + it * 256;      // 0..1023
        int r = f >> 3;
        int cb = (f & 7) * 16;
        uint4 x = make_uint4(0, 0, 0, 0);
        if (r < valid) x = *(const uint4*)(gpk + (size_t)r * 128 + cb);
        *(uint4*)(dst + swz((uint32_t)(r * 128 + cb))) = x;
    }
}

// Vt tile: 32 d-rows x 128 keys, blocked SW128 atoms; VH at dst, VL at dst+8192
__device__ __forceinline__ void load_vt(
    char* dst, const __nv_bfloat16* gvh_t, const __nv_bfloat16* gvl_t,
    int valid, int tid)
{
    #pragma unroll
    for (int it = 0; it < 2; it++) {
        int c = tid + it * 256;
        int d = c >> 4;
        int kc = c & 15;
        uint4 xh = make_uint4(0, 0, 0, 0), xl = make_uint4(0, 0, 0, 0);
        if (kc * 8 < valid) {
            xh = *(const uint4*)(gvh_t + (size_t)d * NN + kc * 8);
            xl = *(const uint4*)(gvl_t + (size_t)d * NN + kc * 8);
        }
        uint32_t off = swz((uint32_t)((d >> 3) * 1024 + (kc >> 3) * 4096
                                      + (d & 7) * 128 + (kc & 7) * 16));
        *(uint4*)(dst + off) = xh;
        *(uint4*)(dst + 8192 + off) = xl;
    }
}

__device__ __forceinline__ void load_kv(
    char* smem, int buf, const uint8_t* gk_rows,
    const __nv_bfloat16* vh_t, const __nv_bfloat16* vl_t,
    size_t vtoff, int kbase, int valid, int tid)
{
    char* kb = smem + SM_KV0 + buf * KV_STRIDE;
    load_rows_packed(kb, gk_rows + (size_t)kbase * 128, valid, tid);
    load_vt(kb + KV_VOFF, vh_t + vtoff + kbase, vl_t + vtoff + kbase, valid, tid);
}

// QK: S = Qh.Kh + Qh.Kl + Ql.Kh  (packed rows: hi k-steps +0,+2; lo +4,+6)
__device__ __forceinline__ void issue_qk(uint32_t qb, uint32_t kb, uint32_t tmem_d) {
    uint64_t qd = mkdesc(qb);
    uint64_t kd = mkdesc(kb);
    mma_ss(tmem_d, qd + 0, kd + 0, IDESC_128, false);
    mma_ss(tmem_d, qd + 2, kd + 2, IDESC_128, true);
    mma_ss(tmem_d, qd + 0, kd + 4, IDESC_128, true);
    mma_ss(tmem_d, qd + 2, kd + 6, IDESC_128, true);
    mma_ss(tmem_d, qd + 4, kd + 0, IDESC_128, true);
    mma_ss(tmem_d, qd + 6, kd + 2, IDESC_128, true);
}

__device__ __forceinline__ void issue_pv(uint32_t phb, uint32_t vb, uint32_t tmem_d, bool first) {
    uint64_t aph = mkdesc(phb);
    uint64_t apl = mkdesc(phb + 32768);
    uint64_t bvh = mkdesc(vb);
    uint64_t bvl = mkdesc(vb + 8192);
    #pragma unroll
    for (int term = 0; term < 3; term++) {
        uint64_t Aa = (term == 2) ? apl : aph;
        uint64_t Bb = (term == 1) ? bvl : bvh;
        #pragma unroll
        for (int ks = 0; ks < 8; ks++) {
            uint64_t ad = Aa + (ks < 4 ? 2 * ks : 1024 + 2 * (ks - 4));
            uint64_t bd = Bb + (ks < 4 ? 2 * ks : 256 + 2 * (ks - 4));
            mma_ss(tmem_d, ad, bd, IDESC_PV, !(first && term == 0 && ks == 0));
        }
    }
}

__device__ __forceinline__ void epilogue_tile(
    char* smem, uint32_t tmem_s, int row, int half, int valid, float& lacc)
{
    const uint32_t xorc = (uint32_t)((row & 7) << 4);
    const uint32_t base0 = (uint32_t)((row >> 3) * 1024 + (row & 7) * 128);
    #pragma unroll
    for (int cc = 0; cc < 2; cc++) {
        const int c0 = half * 64 + cc * 32;
        uint32_t sreg[32];
        LDTM_X32(sreg, tmem_s + c0);
        TC_WAIT_LD();
        const uint32_t cbase = base0 + (uint32_t)((c0 >> 6) * 16384);
        const uint32_t kk0 = (uint32_t)((c0 & 63) * 2);
        if (valid >= c0 + 32) {
            #pragma unroll
            for (int j = 0; j < 32; j += 2) {
                float e0 = ex2f(__uint_as_float(sreg[j]));
                float e1 = ex2f(__uint_as_float(sreg[j + 1]));
                lacc += e0 + e1;
                uint32_t hp = pack_bf(e1, e0);
                float h0 = __uint_as_float(hp << 16);
                float h1 = __uint_as_float(hp & 0xFFFF0000u);
                uint32_t lp = pack_bf(e1 - h1, e0 - h0);
                uint32_t off = cbase + ((kk0 + 2 * j) ^ xorc);
                *(uint32_t*)(smem + SM_PH + off) = hp;
                *(uint32_t*)(smem + SM_PL + off) = lp;
            }
        } else {
            #pragma unroll
            for (int j = 0; j < 32; j += 2) {
                int col = c0 + j;
                float e0 = (col < valid)     ? ex2f(__uint_as_float(sreg[j]))     : 0.f;
                float e1 = (col + 1 < valid) ? ex2f(__uint_as_float(sreg[j + 1])) : 0.f;
                lacc += e0 + e1;
                uint32_t hp = pack_bf(e1, e0);
                float h0 = __uint_as_float(hp << 16);
                float h1 = __uint_as_float(hp & 0xFFFF0000u);
                uint32_t lp = pack_bf(e1 - h1, e0 - h0);
                uint32_t off = cbase + ((kk0 + 2 * j) ^ xorc);
                *(uint32_t*)(smem + SM_PH + off) = hp;
                *(uint32_t*)(smem + SM_PL + off) = lp;
            }
        }
    }
}
#endif  // __CUDA_ARCH_FEAT_SM103_ALL

__global__ void __launch_bounds__(256, 1) attn_kernel(
    const uint8_t* __restrict__ gq, const uint8_t* __restrict__ gk,
    const __nv_bfloat16* __restrict__ vh_t, const __nv_bfloat16* __restrict__ vl_t,
    float* __restrict__ ao)
{
    extern __shared__ __align__(1024) char smem[];
    const int tid = threadIdx.x;
    const int b = blockIdx.z, h = blockIdx.y;
    const size_t rowoff = (size_t)(b * H_ + h) * NN;          // packed-row index base
    const size_t vtoff = (size_t)(b * H_ + h) * HD_ * NN;     // Vt layout
    const int q0 = blockIdx.x * 128;
    const int qvalid = min(128, NN - q0);

#if defined(__CUDA_ARCH_FEAT_SM103_ALL)
    const uint32_t sbase = smem_u32(smem);
    const int wid = tid >> 5;
    const int lane = tid & 31;
    const int half = wid >> 2;
    const int row = (wid & 3) * 32 + lane;
    const uint8_t* gk_rows = gk + rowoff * 128;

    if (wid == 0) TC_ALLOC(sbase + SM_TM, 512);
    if (tid == 0) { MB_INIT(sbase + SM_MBS, 1); MB_INIT(sbase + SM_MBO, 1); }
    __syncthreads();
    uint32_t tmem;
    asm volatile("ld.shared.b32 %0, [%1];" : "=r"(tmem) : "r"(sbase + SM_TM));

    // prologue: Q + KV tiles 0,1; then QK(0)
    load_rows_packed(smem + SM_Q, gq + (rowoff + q0) * 128, qvalid, tid);
    load_kv(smem, 0, gk_rows, vh_t, vl_t, vtoff, 0, 128, tid);
    load_kv(smem, 1, gk_rows, vh_t, vl_t, vtoff, 128, 128, tid);
    FENCE_ASYNC();
    __syncthreads();
    if (wid == 0 && elect1()) {
        issue_qk(sbase + SM_Q, sbase + SM_KV0, tmem + TM_S0);
        TC_COMMIT(sbase + SM_MBS);
    }

    uint32_t pS = 0, pO = 0;
    float lacc1 = 0.f, lacc2 = 0.f;

    for (int t = 0; t < NTALL; t++) {
        const int valid = (t < NT1) ? min(128, NKD - t * 128) : NKE_;
        mb_wait(sbase + SM_MBS, pS); pS ^= 1;
        TC_FENCE_AFTER();
        if (t + 1 < NTALL && wid == 0 && elect1()) {
            issue_qk(sbase + SM_Q, sbase + SM_KV0 + ((t + 1) & 3) * KV_STRIDE,
                     tmem + (((t + 1) & 1) ? TM_S1 : TM_S0));
            TC_COMMIT(sbase + SM_MBS);
        }
        if (t >= 1) { mb_wait(sbase + SM_MBO, pO); pO ^= 1; TC_FENCE_AFTER(); }
        if (t + 2 < NTALL) {
            int nb = (t + 2 < NT1) ? (t + 2) * 128 : NKD;
            int nv = (t + 2 < NT1) ? min(128, NKD - nb) : NKE_;
            load_kv(smem, (t + 2) & 3, gk_rows, vh_t, vl_t, vtoff, nb, nv, tid);
        }
        epilogue_tile(smem, tmem + ((t & 1) ? TM_S1 : TM_S0), row, half, valid,
                      (t < NT1) ? lacc1 : lacc2);
        TC_FENCE_BEFORE();
        FENCE_ASYNC();
        __syncthreads();
        if (wid == 0 && elect1()) {
            issue_pv(sbase + SM_PH,
                     sbase + SM_KV0 + (t & 3) * KV_STRIDE + KV_VOFF,
                     tmem + ((t < NT1) ? TM_O1 : TM_O2),
                     (t == 0) || (t == NT1));
            TC_COMMIT(sbase + SM_MBO);
        }
    }

    float* lsum1 = (float*)(smem + SM_LSUM1);
    float* lsum2 = (float*)(smem + SM_LSUM2);
    if (half == 1) { lsum1[row] = lacc1; lsum2[row] = lacc2; }
    __syncthreads();

    mb_wait(sbase + SM_MBO, pO); pO ^= 1;
    TC_FENCE_AFTER();
    if (half == 0) {
        float l1 = lacc1 + lsum1[row];
        float l2 = lacc2 + lsum2[row];
        uint32_t o1[32], o2[32];
        LDTM_X32(o1, tmem + TM_O1);
        LDTM_X32(o2, tmem + TM_O2);
        TC_WAIT_LD();
        float inv1 = 1.f / l1, inv2 = 1.f / l2;
        if (row < qvalid) {
            float* orow = ao + ((size_t)(b * NN + q0 + row)) * 256 + h * 32;
            #pragma unroll
            for (int d = 0; d < 32; d += 4) {
                float4 tv;
                tv.x = __uint_as_float(o1[d])     * inv1 + __uint_as_float(o2[d])     * inv2;
                tv.y = __uint_as_float(o1[d + 1]) * inv1 + __uint_as_float(o2[d + 1]) * inv2;
                tv.z = __uint_as_float(o1[d + 2]) * inv1 + __uint_as_float(o2[d + 2]) * inv2;
                tv.w = __uint_as_float(o1[d + 3]) * inv1 + __uint_as_float(o2[d + 3]) * inv2;
                *(float4*)(orow + d) = tv;
            }
        }
    }
    __syncthreads();
    if (wid == 0) {
        TC_RELINQ();
        TC_DEALLOC(tmem, 512);
    }
#else
    // scalar fallback with packed Q/K
    const int qi = q0 + (tid & 127);
    const int hsel = tid >> 7;
    const bool active = qi < NN;

    float q[HD_];
    if (active) {
        const uint8_t* qr = gq + (rowoff + qi) * 128;
        #pragma unroll
        for (int d = 0; d < HD_; d++)
            q[d] = __bfloat162float(*(const __nv_bfloat16*)(qr + d * 2))
                 + __bfloat162float(*(const __nv_bfloat16*)(qr + 64 + d * 2));
    } else {
        #pragma unroll
        for (int d = 0; d < HD_; d++) q[d] = 0.f;
    }

    float o1[HD_] = {}, o2[HD_] = {};
    float l1 = 0.f, l2 = 0.f;
    const int ks = hsel ? 2048 : 0;
    const int ke = hsel ? NKD : 2048;
    if (active) {
        for (int j = ks; j < ke; j++) {
            const uint8_t* kr = gk + (rowoff + j) * 128;
            float s = 0.f;
            #pragma unroll
            for (int d = 0; d < HD_; d++)
                s += q[d] * (__bfloat162float(*(const __nv_bfloat16*)(kr + d * 2))
                           + __bfloat162float(*(const __nv_bfloat16*)(kr + 64 + d * 2)));
            float e = ex2f(s);
            l1 += e;
            #pragma unroll
            for (int d = 0; d < HD_; d++) {
                size_t vi = vtoff + (size_t)d * NN + j;
                o1[d] += e * (__bfloat162float(vh_t[vi]) + __bfloat162float(vl_t[vi]));
            }
        }
        if (hsel == 1) {
            for (int j = NKD; j < NN; j++) {
                const uint8_t* kr = gk + (rowoff + j) * 128;
                float s = 0.f;
                #pragma unroll
                for (int d = 0; d < HD_; d++)
                    s += q[d] * (__bfloat162float(*(const __nv_bfloat16*)(kr + d * 2))
                               + __bfloat162float(*(const __nv_bfloat16*)(kr + 64 + d * 2)));
                float e = ex2f(s);
                l2 += e;
                #pragma unroll
                for (int d = 0; d < HD_; d++) {
                    size_t vi = vtoff + (size_t)d * NN + j;
                    o2[d] += e * (__bfloat162float(vh_t[vi]) + __bfloat162float(vl_t[vi]));
                }
            }
        }
    }
    float* sh = (float*)smem;
    float* shl = sh + 128 * HD_;
    float* sh2 = shl + 128;
    float* sh2l = sh2 + 128 * HD_;
    if (hsel == 1) {
        int r = tid & 127;
        #pragma unroll
        for (int d = 0; d < HD_; d++) { sh[r * HD_ + d] = o1[d]; sh2[r * HD_ + d] = o2[d]; }
        shl[r] = l1; sh2l[r] = l2;
    }
    __syncthreads();
    if (hsel == 0 && active) {
        int r = tid & 127;
        float lt = l1 + shl[r];
        float inv1 = 1.f / lt;
        float inv2 = 1.f / sh2l[r];
        float* orow = ao + ((size_t)(b * NN + qi)) * 256 + h * HD_;
        #pragma unroll
        for (int d = 0; d < HD_; d++)
            orow[d] = (o1[d] + sh[r * HD_ + d]) * inv1 + sh2[r * HD_ + d] * inv2;
    }
#endif
}

// ---------------- launch ----------------
extern "C" void kernel_launch(void* const* d_in, const int* in_sizes, int n_in,
                              void* d_out, int out_size)
{
    const float* q    = (const float*)d_in[0];
    const float* k    = (const float*)d_in[1];
    const float* v    = (const float*)d_in[2];
    const float* fimg = (const float*)d_in[3];
    const float* ftxt = (const float*)d_in[4];
    const float* Wq   = (const float*)d_in[5];
    const float* bq   = (const float*)d_in[6];
    const float* Wk   = (const float*)d_in[7];
    const float* bk   = (const float*)d_in[8];
    const float* Wv   = (const float*)d_in[9];
    const float* bv   = (const float*)d_in[10];
    const float* Wo   = (const float*)d_in[11];
    const float* bo   = (const float*)d_in[12];
    float* out = (float*)d_out;

    uint8_t *gq, *gk;
    __nv_bfloat16 *gvh, *gvl;
    float* ao;
    cudaGetSymbolAddress((void**)&gq, g_q);
    cudaGetSymbolAddress((void**)&gk, g_k);
    cudaGetSymbolAddress((void**)&gvh, g_vh);
    cudaGetSymbolAddress((void**)&gvl, g_vl);
    cudaGetSymbolAddress((void**)&ao, g_ao);

    cudaFuncSetAttribute(gemm_tc, cudaFuncAttributeMaxDynamicSharedMemorySize, GS_TOTAL);
    cudaFuncSetAttribute(attn_kernel, cudaFuncAttributeMaxDynamicSharedMemorySize, SMEM_TOTAL);

    // fused QKV projections (z: 0=Q,1=K,2=V)
    gemm_tc<<<dim3(MT, 3), 256, GS_TOTAL>>>(
        q, k, v, Wq, Wk, Wv, bq, bk, bv,
        gq, gk, gvh, gvl, nullptr, 1, fimg, ftxt);

    dim3 ga(33, H_, BB);
    attn_kernel<<<ga, 256, SMEM_TOTAL>>>(gq, gk, gvh, gvl, ao);

    // output projection
    gemm_tc<<<dim3(MT, 1), 256, GS_TOTAL>>>(
        ao, nullptr, nullptr, Wo, nullptr, nullptr, bo, nullptr, nullptr,
        gq, gk, gvh, gvl, out, 0, fimg, ftxt);
}

// round 11
// speedup vs baseline: 2.1711x; 1.2220x over previous
#include <cuda_runtime.h>
#include <cuda_bf16.h>
#include <stdint.h>
#include <math.h>

#define D_    256
#define H_    8
#define HD_   32
#define NIMG_ 4096
#define NN    4112
#define BB    2
#define NKE_  64
#define MROWS (BB * NN)      /* 8224 */
#define NKD   (NN - NKE_)    /* 4048 */
#define NT1   32             /* ceil(4048/128) */
#define NTALL 33             /* 32 dense tiles + 1 mem tile */
#define MT    65             /* ceil(8224/128) GEMM row tiles */

// ---------------- global scratch (no allocs allowed) ----------------
// Q/K packed: per (b,h,n) one 128B row: hi bf16 d0..31 at [0,64), lo at [64,128)
__device__ uint8_t g_q[(size_t)BB * H_ * NN * 128];
__device__ uint8_t g_k[(size_t)BB * H_ * NN * 128];
// V transposed: [b][h][d][key], hi and lo arrays
__device__ __nv_bfloat16 g_vh[(size_t)BB * H_ * HD_ * NN];
__device__ __nv_bfloat16 g_vl[(size_t)BB * H_ * HD_ * NN];
__device__ float g_ao[(size_t)MROWS * D_];

// scale: 1/sqrt(32) * log2(e)  (so softmax exp == exp2)
#define QSCALE (0.17677669529663687f * 1.4426950408889634f)

// idesc kind::f16: dtypeF32(1<<4) | aBF16(1<<7) | bBF16(1<<10) | (N/8)<<17 | (M/16)<<24
#define IDESC_128 0x8200490u  /* M=128 N=128 */
#define IDESC_PV  0x8080490u  /* M=128 N=32  */

// ---------------- arch-portable helpers ----------------
__device__ __forceinline__ uint32_t smem_u32(const void* p) {
    uint32_t a;
    asm("{ .reg .u64 t; cvta.to.shared.u64 t, %1; cvt.u32.u64 %0, t; }" : "=r"(a) : "l"(p));
    return a;
}
__device__ __forceinline__ float ex2f(float x) {
    float y; asm("ex2.approx.ftz.f32 %0, %1;" : "=f"(y) : "f"(x)); return y;
}
__device__ __forceinline__ uint32_t swz(uint32_t b) { return b ^ ((b >> 3) & 0x70); }
__device__ __forceinline__ uint32_t pack_bf(float hi, float lo) {
    uint32_t r; asm("cvt.rn.bf16x2.f32 %0, %1, %2;" : "=r"(r) : "f"(hi), "f"(lo)); return r;
}

// ---------------- tcgen05 helpers: sm_103a ONLY ----------------
#if defined(__CUDA_ARCH_FEAT_SM103_ALL)
__device__ __forceinline__ bool elect1() {
    uint32_t p;
    asm volatile("{ .reg .pred p; elect.sync _|p, 0xFFFFFFFF; selp.b32 %0, 1, 0, p; }" : "=r"(p));
    return p != 0;
}
__device__ __forceinline__ uint64_t mkdesc(uint32_t addr) {
    return ((uint64_t)2 << 61) | ((uint64_t)1 << 46) | ((uint64_t)64 << 32)
         | ((uint64_t)1 << 16) | ((addr >> 4) & 0x3FFF);
}
__device__ __forceinline__ void mma_ss(uint32_t d, uint64_t a, uint64_t b, uint32_t idesc, bool acc) {
    uint32_t en = acc ? 1u : 0u;
    asm volatile(
        "{\n\t.reg .pred p;\n\tsetp.ne.u32 p, %5, 0;\n\t"
        "tcgen05.mma.cta_group::1.kind::f16 [%0], %1, %2, %3, {%4,%4,%4,%4}, p;\n\t}"
        :: "r"(d), "l"(a), "l"(b), "r"(idesc), "r"(0u), "r"(en) : "memory");
}
#define TC_COMMIT(mbar) \
    asm volatile("tcgen05.commit.cta_group::1.mbarrier::arrive::one.shared::cluster.b64 [%0];" :: "r"(mbar) : "memory")
#define TC_ALLOC(smem_addr, n) \
    asm volatile("tcgen05.alloc.cta_group::1.sync.aligned.shared::cta.b32 [%0], %1;" :: "r"(smem_addr), "r"(n) : "memory")
#define TC_DEALLOC(tmem, n) \
    asm volatile("tcgen05.dealloc.cta_group::1.sync.aligned.b32 %0, %1;" :: "r"(tmem), "r"(n))
#define TC_RELINQ() asm volatile("tcgen05.relinquish_alloc_permit.cta_group::1.sync.aligned;")
#define TC_WAIT_LD() asm volatile("tcgen05.wait::ld.sync.aligned;" ::: "memory")
#define TC_FENCE_AFTER() asm volatile("tcgen05.fence::after_thread_sync;" ::: "memory")
#define TC_FENCE_BEFORE() asm volatile("tcgen05.fence::before_thread_sync;" ::: "memory")
#define FENCE_ASYNC() asm volatile("fence.proxy.async.shared::cta;" ::: "memory")
#define MB_INIT(addr, cnt) \
    asm volatile("mbarrier.init.shared.b64 [%0], %1;" :: "r"(addr), "r"(cnt) : "memory")

__device__ __forceinline__ void mb_wait(uint32_t mbar, uint32_t parity) {
    uint32_t done;
    asm volatile(
        "{\n\t.reg .pred p;\n\t"
        "mbarrier.try_wait.parity.acquire.cta.shared::cta.b64 p, [%1], %2;\n\t"
        "selp.b32 %0, 1, 0, p;\n\t}"
        : "=r"(done) : "r"(mbar), "r"(parity) : "memory");
    if (!done) {
        asm volatile(
            "{\n\t.reg .pred P1;\n\t"
            "WL_%=:\n\t"
            "mbarrier.try_wait.parity.acquire.cta.shared::cta.b64 P1, [%0], %1, 0x989680;\n\t"
            "@P1 bra.uni WD_%=;\n\t"
            "bra.uni WL_%=;\n\t"
            "WD_%=:\n\t}"
            :: "r"(mbar), "r"(parity) : "memory");
    }
}

#define LDTM_X32(r, addr) \
    asm volatile( \
        "tcgen05.ld.sync.aligned.32x32b.x32.b32 " \
        "{%0,%1,%2,%3,%4,%5,%6,%7,%8,%9,%10,%11,%12,%13,%14,%15," \
        "%16,%17,%18,%19,%20,%21,%22,%23,%24,%25,%26,%27,%28,%29,%30,%31}, [%32];" \
        : "=r"((r)[0]),"=r"((r)[1]),"=r"((r)[2]),"=r"((r)[3]),"=r"((r)[4]),"=r"((r)[5]), \
          "=r"((r)[6]),"=r"((r)[7]),"=r"((r)[8]),"=r"((r)[9]),"=r"((r)[10]),"=r"((r)[11]), \
          "=r"((r)[12]),"=r"((r)[13]),"=r"((r)[14]),"=r"((r)[15]),"=r"((r)[16]),"=r"((r)[17]), \
          "=r"((r)[18]),"=r"((r)[19]),"=r"((r)[20]),"=r"((r)[21]),"=r"((r)[22]),"=r"((r)[23]), \
          "=r"((r)[24]),"=r"((r)[25]),"=r"((r)[26]),"=r"((r)[27]),"=r"((r)[28]),"=r"((r)[29]), \
          "=r"((r)[30]),"=r"((r)[31]) : "r"(addr))
#endif  // __CUDA_ARCH_FEAT_SM103_ALL

// ================= tcgen05 projection GEMM (R8 single-buffer version) =================
// C[m,j] = sum_i A[m,i]*W[j,i] + bias[j]; M tile 128/CTA; K=256 in 4 chunks of 64.
// 3-term bf16 hi/lo emulation. modes: 0 fp32 out; 1 Q(rope+QSCALE->packed);
// 2 K(rope->packed); 3 V(transposed hi/lo).
#define GS_AH   0        /* 16384 */
#define GS_AL   16384    /* 16384 */
#define GS_WH   32768    /* 32768 */
#define GS_WL   65536    /* 32768 */
#define GS_FREQ 98304    /* 16384: float2 [cidx 16][row 128] */
#define GS_BIAS 114688   /* 1024 */
#define GS_TM   115712
#define GS_MB   115720
#define GS_TOTAL 115840

__global__ void __launch_bounds__(256) gemm_tc(
    const float* __restrict__ A0, const float* __restrict__ A1, const float* __restrict__ A2,
    const float* __restrict__ W0, const float* __restrict__ W1, const float* __restrict__ W2,
    const float* __restrict__ B0, const float* __restrict__ B1, const float* __restrict__ B2,
    uint8_t* __restrict__ gq, uint8_t* __restrict__ gk,
    __nv_bfloat16* __restrict__ gvh, __nv_bfloat16* __restrict__ gvl,
    float* __restrict__ outf, int qkv,
    const float* __restrict__ fimg, const float* __restrict__ ftxt)
{
    extern __shared__ __align__(1024) char smem[];
    const int tid = threadIdx.x;
    const int m0 = blockIdx.x * 128;
    int mode;
    const float *A, *W, *bias;
    if (qkv) {
        mode = blockIdx.y + 1;
        if (blockIdx.y == 0)      { A = A0; W = W0; bias = B0; }
        else if (blockIdx.y == 1) { A = A1; W = W1; bias = B1; }
        else                      { A = A2; W = W2; bias = B2; }
    } else { mode = 0; A = A0; W = W0; bias = B0; }

#if defined(__CUDA_ARCH_FEAT_SM103_ALL)
    const uint32_t sb = smem_u32(smem);
    const int wid = tid >> 5;
    const int lane = tid & 31;

    if (wid == 0) TC_ALLOC(sb + GS_TM, 256);
    if (tid == 0) MB_INIT(sb + GS_MB, 1);
    __syncthreads();
    uint32_t tmem;
    asm volatile("ld.shared.b32 %0, [%1];" : "=r"(tmem) : "r"(sb + GS_TM));

    // stage bias
    if (tid < 256) *(float*)(smem + GS_BIAS + tid * 4) = bias[tid];
    // stage freqs (modes 1,2): sfreq[cidx][row] float2
    if (mode == 1 || mode == 2) {
        int r = tid >> 1;
        int hh = tid & 1;
        int m = m0 + r;
        #pragma unroll
        for (int cc = 0; cc < 8; cc++) {
            int cidx = hh * 8 + cc;
            float2 f = make_float2(1.f, 0.f);
            if (m < MROWS) {
                int bb = (m >= NN) ? 1 : 0;
                int n = m - bb * NN;
                f = (n < NIMG_) ? *(const float2*)(fimg + ((size_t)n * 16 + cidx) * 2)
                                : *(const float2*)(ftxt + ((size_t)(n - NIMG_) * 16 + cidx) * 2);
            }
            *(float2*)(smem + GS_FREQ + ((size_t)cidx * 128 + r) * 8) = f;
        }
    }

    uint32_t par = 0;
    for (int c = 0; c < 4; c++) {
        if (c > 0) { mb_wait(sb + GS_MB, par); par ^= 1; }
        const int k0 = c * 64;
        // load A chunk: 128 rows x 64 floats -> hi/lo bf16
        #pragma unroll
        for (int it = 0; it < 8; it++) {
            int i = tid + it * 256;
            int r = i >> 4;
            int c4 = (i & 15) * 4;
            float4 va = make_float4(0.f, 0.f, 0.f, 0.f);
            if (m0 + r < MROWS) va = *(const float4*)(A + (size_t)(m0 + r) * 256 + k0 + c4);
            uint32_t h01 = pack_bf(va.y, va.x);
            uint32_t h23 = pack_bf(va.w, va.z);
            float hx = __uint_as_float(h01 << 16), hy = __uint_as_float(h01 & 0xFFFF0000u);
            float hz = __uint_as_float(h23 << 16), hw = __uint_as_float(h23 & 0xFFFF0000u);
            uint32_t l01 = pack_bf(va.y - hy, va.x - hx);
            uint32_t l23 = pack_bf(va.w - hw, va.z - hz);
            uint32_t off = swz((uint32_t)(r * 128 + c4 * 2));
            *(uint2*)(smem + GS_AH + off) = make_uint2(h01, h23);
            *(uint2*)(smem + GS_AL + off) = make_uint2(l01, l23);
        }
        // load W chunk: 256 rows x 64 floats
        #pragma unroll
        for (int it = 0; it < 16; it++) {
            int i = tid + it * 256;
            int r = i >> 4;
            int c4 = (i & 15) * 4;
            float4 vw = *(const float4*)(W + (size_t)r * 256 + k0 + c4);
            uint32_t h01 = pack_bf(vw.y, vw.x);
            uint32_t h23 = pack_bf(vw.w, vw.z);
            float hx = __uint_as_float(h01 << 16), hy = __uint_as_float(h01 & 0xFFFF0000u);
            float hz = __uint_as_float(h23 << 16), hw = __uint_as_float(h23 & 0xFFFF0000u);
            uint32_t l01 = pack_bf(vw.y - hy, vw.x - hx);
            uint32_t l23 = pack_bf(vw.w - hw, vw.z - hz);
            uint32_t off = swz((uint32_t)(r * 128 + c4 * 2));
            *(uint2*)(smem + GS_WH + off) = make_uint2(h01, h23);
            *(uint2*)(smem + GS_WL + off) = make_uint2(l01, l23);
        }
        FENCE_ASYNC();
        __syncthreads();
        if (wid == 0 && elect1()) {
            uint64_t ah = mkdesc(sb + GS_AH), al = mkdesc(sb + GS_AL);
            uint64_t wh = mkdesc(sb + GS_WH), wl = mkdesc(sb + GS_WL);
            #pragma unroll
            for (int nh = 0; nh < 2; nh++) {
                uint32_t dcol = tmem + nh * 128;
                uint64_t bo = (uint64_t)nh * 1024;
                #pragma unroll
                for (int ks = 0; ks < 4; ks++) {
                    uint64_t a_h = ah + 2 * ks, a_l = al + 2 * ks;
                    uint64_t b_h = wh + bo + 2 * ks, b_l = wl + bo + 2 * ks;
                    mma_ss(dcol, a_h, b_h, IDESC_128, !(c == 0 && ks == 0));
                    mma_ss(dcol, a_h, b_l, IDESC_128, true);
                    mma_ss(dcol, a_l, b_h, IDESC_128, true);
                }
            }
            TC_COMMIT(sb + GS_MB);
        }
    }
    mb_wait(sb + GS_MB, par);
    TC_FENCE_AFTER();

    // epilogue: warp w -> rows (w&3)*32+lane, cols (w>>2)*128 + cc*32
    {
        const int r = (wid & 3) * 32 + lane;
        const int m = m0 + r;
        const int cb0 = (wid >> 2) * 128;
        const bool mok = (m < MROWS);
        int bb = (m >= NN) ? 1 : 0;
        int n = m - bb * NN;
        #pragma unroll
        for (int cc = 0; cc < 4; cc++) {
            const int c0 = cb0 + cc * 32;
            uint32_t s[32];
            LDTM_X32(s, tmem + c0);
            TC_WAIT_LD();
            if (!mok) continue;
            if (mode == 0) {
                #pragma unroll
                for (int j = 0; j < 32; j++) {
                    float bv = *(const float*)(smem + GS_BIAS + (c0 + j) * 4);
                    outf[(size_t)m * 256 + c0 + j] = __uint_as_float(s[j]) + bv;
                }
            } else if (mode == 3) {
                const int head = c0 >> 5;
                #pragma unroll
                for (int j = 0; j < 32; j++) {
                    float bv = *(const float*)(smem + GS_BIAS + (c0 + j) * 4);
                    float val = __uint_as_float(s[j]) + bv;
                    __nv_bfloat16 hb = __float2bfloat16(val);
                    float rr = val - __bfloat162float(hb);
                    size_t dst = ((size_t)(bb * H_ + head) * HD_ + j) * NN + n;
                    gvh[dst] = hb;
                    gvl[dst] = __float2bfloat16(rr);
                }
            } else {
                const int head = c0 >> 5;
                uint8_t* gout = (mode == 1) ? gq : gk;
                uint8_t* rowp = gout + ((size_t)(bb * H_ + head) * NN + n) * 128;
                #pragma unroll
                for (int p = 0; p < 16; p++) {
                    float b0v = *(const float*)(smem + GS_BIAS + (c0 + 2 * p) * 4);
                    float b1v = *(const float*)(smem + GS_BIAS + (c0 + 2 * p + 1) * 4);
                    float x0 = __uint_as_float(s[2 * p]) + b0v;
                    float x1 = __uint_as_float(s[2 * p + 1]) + b1v;
                    float2 f = *(const float2*)(smem + GS_FREQ + ((size_t)p * 128 + r) * 8);
                    float y0 = x0 * f.x - x1 * f.y;
                    float y1 = x0 * f.y + x1 * f.x;
                    if (mode == 1) { y0 *= QSCALE; y1 *= QSCALE; }
                    uint32_t hp = pack_bf(y1, y0);
                    float h0 = __uint_as_float(hp << 16);
                    float h1 = __uint_as_float(hp & 0xFFFF0000u);
                    uint32_t lp = pack_bf(y1 - h1, y0 - h0);
                    *(uint32_t*)(rowp + p * 4) = hp;
                    *(uint32_t*)(rowp + 64 + p * 4) = lp;
                }
            }
        }
    }
    __syncthreads();
    if (wid == 0) {
        TC_RELINQ();
        TC_DEALLOC(tmem, 256);
    }
#else
    // naive fallback (only if sm_103a cubin absent)
    for (int idx = tid; idx < 128 * 128; idx += 256) {
        int r = idx >> 7;
        int p = idx & 127;
        int m = m0 + r;
        if (m >= MROWS) continue;
        int j0_ = p * 2;
        float s0 = bias[j0_], s1 = bias[j0_ + 1];
        for (int k2 = 0; k2 < 256; k2++) {
            float a = A[(size_t)m * 256 + k2];
            s0 += a * W[(size_t)j0_ * 256 + k2];
            s1 += a * W[(size_t)(j0_ + 1) * 256 + k2];
        }
        int bb = (m >= NN) ? 1 : 0;
        int n = m - bb * NN;
        if (mode == 1 || mode == 2) {
            int cidx = (j0_ & 31) >> 1;
            const float* f = (n < NIMG_) ? (fimg + ((size_t)n * 16 + cidx) * 2)
                                         : (ftxt + ((size_t)(n - NIMG_) * 16 + cidx) * 2);
            float y0 = s0 * f[0] - s1 * f[1];
            float y1 = s0 * f[1] + s1 * f[0];
            if (mode == 1) { y0 *= QSCALE; y1 *= QSCALE; }
            int head = j0_ >> 5, d = j0_ & 31;
            uint8_t* gout = (mode == 1) ? gq : gk;
            uint8_t* rowp = gout + ((size_t)(bb * H_ + head) * NN + n) * 128;
            uint32_t hp = pack_bf(y1, y0);
            float h0 = __uint_as_float(hp << 16), h1 = __uint_as_float(hp & 0xFFFF0000u);
            uint32_t lp = pack_bf(y1 - h1, y0 - h0);
            *(uint32_t*)(rowp + (d >> 1) * 4) = hp;
            *(uint32_t*)(rowp + 64 + (d >> 1) * 4) = lp;
        } else if (mode == 3) {
            int head = j0_ >> 5, d = j0_ & 31;
            #pragma unroll
            for (int e = 0; e < 2; e++) {
                float val = e ? s1 : s0;
                __nv_bfloat16 hb = __float2bfloat16(val);
                size_t dst = ((size_t)(bb * H_ + head) * HD_ + d + e) * NN + n;
                gvh[dst] = hb;
                gvl[dst] = __float2bfloat16(val - __bfloat162float(hb));
            }
        } else {
            outf[(size_t)m * 256 + j0_] = s0;
            outf[(size_t)m * 256 + j0_ + 1] = s1;
        }
    }
#endif
}

// ================= attention (R5 structure, packed Q/K, STS.128 P) =================
#define SM_Q     0
#define SM_KV0   16384
#define KV_STRIDE 32768
#define KV_VOFF  16384
#define SM_PH    147456
#define SM_PL    180224
#define SM_TM    212992
#define SM_MBS   213000
#define SM_MBO   213008
#define SM_LSUM1 213056
#define SM_LSUM2 213568
#define SMEM_TOTAL 214080

#define TM_S0 0
#define TM_S1 128
#define TM_O1 256
#define TM_O2 288

#if defined(__CUDA_ARCH_FEAT_SM103_ALL)
__device__ __forceinline__ void load_rows_packed(
    char* dst, const uint8_t* gpk, int valid, int tid)
{
    #pragma unroll
    for (int it = 0; it < 4; it++) {
        int f = tid + it * 256;
        int r = f >> 3;
        int cb = (f & 7) * 16;
        uint4 x = make_uint4(0, 0, 0, 0);
        if (r < valid) x = *(const uint4*)(gpk + (size_t)r * 128 + cb);
        *(uint4*)(dst + swz((uint32_t)(r * 128 + cb))) = x;
    }
}

__device__ __forceinline__ void load_vt(
    char* dst, const __nv_bfloat16* gvh_t, const __nv_bfloat16* gvl_t,
    int valid, int tid)
{
    #pragma unroll
    for (int it = 0; it < 2; it++) {
        int c = tid + it * 256;
        int d = c >> 4;
        int kc = c & 15;
        uint4 xh = make_uint4(0, 0, 0, 0), xl = make_uint4(0, 0, 0, 0);
        if (kc * 8 < valid) {
            xh = *(const uint4*)(gvh_t + (size_t)d * NN + kc * 8);
            xl = *(const uint4*)(gvl_t + (size_t)d * NN + kc * 8);
        }
        uint32_t off = swz((uint32_t)((d >> 3) * 1024 + (kc >> 3) * 4096
                                      + (d & 7) * 128 + (kc & 7) * 16));
        *(uint4*)(dst + off) = xh;
        *(uint4*)(dst + 8192 + off) = xl;
    }
}

__device__ __forceinline__ void load_kv(
    char* smem, int buf, const uint8_t* gk_rows,
    const __nv_bfloat16* vh_t, const __nv_bfloat16* vl_t,
    size_t vtoff, int kbase, int valid, int tid)
{
    char* kb = smem + SM_KV0 + buf * KV_STRIDE;
    load_rows_packed(kb, gk_rows + (size_t)kbase * 128, valid, tid);
    load_vt(kb + KV_VOFF, vh_t + vtoff + kbase, vl_t + vtoff + kbase, valid, tid);
}

__device__ __forceinline__ void issue_qk(uint32_t qb, uint32_t kb, uint32_t tmem_d) {
    uint64_t qd = mkdesc(qb);
    uint64_t kd = mkdesc(kb);
    mma_ss(tmem_d, qd + 0, kd + 0, IDESC_128, false);
    mma_ss(tmem_d, qd + 2, kd + 2, IDESC_128, true);
    mma_ss(tmem_d, qd + 0, kd + 4, IDESC_128, true);
    mma_ss(tmem_d, qd + 2, kd + 6, IDESC_128, true);
    mma_ss(tmem_d, qd + 4, kd + 0, IDESC_128, true);
    mma_ss(tmem_d, qd + 6, kd + 2, IDESC_128, true);
}

__device__ __forceinline__ void issue_pv(uint32_t phb, uint32_t vb, uint32_t tmem_d, bool first) {
    uint64_t aph = mkdesc(phb);
    uint64_t apl = mkdesc(phb + 32768);
    uint64_t bvh = mkdesc(vb);
    uint64_t bvl = mkdesc(vb + 8192);
    #pragma unroll
    for (int term = 0; term < 3; term++) {
        uint64_t Aa = (term == 2) ? apl : aph;
        uint64_t Bb = (term == 1) ? bvl : bvh;
        #pragma unroll
        for (int ks = 0; ks < 8; ks++) {
            uint64_t ad = Aa + (ks < 4 ? 2 * ks : 1024 + 2 * (ks - 4));
            uint64_t bd = Bb + (ks < 4 ? 2 * ks : 256 + 2 * (ks - 4));
            mma_ss(tmem_d, ad, bd, IDESC_PV, !(first && term == 0 && ks == 0));
        }
    }
}

// Softmax epilogue with STS.128 P writes (8 cols per store, conflict-phased clean).
__device__ __forceinline__ void epilogue_tile(
    char* smem, uint32_t tmem_s, int row, int half, int valid, float& lacc)
{
    const uint32_t xorc = (uint32_t)((row & 7) << 4);
    const uint32_t base0 = (uint32_t)((row >> 3) * 1024 + (row & 7) * 128);
    #pragma unroll
    for (int cc = 0; cc < 2; cc++) {
        const int c0 = half * 64 + cc * 32;
        uint32_t sreg[32];
        LDTM_X32(sreg, tmem_s + c0);
        TC_WAIT_LD();
        const uint32_t cbase = base0 + (uint32_t)((c0 >> 6) * 16384);
        const uint32_t kk0 = (uint32_t)((c0 & 63) * 2);
        if (valid >= c0 + 32) {
            #pragma unroll
            for (int g = 0; g < 4; g++) {
                float e[8];
                #pragma unroll
                for (int j = 0; j < 8; j++) {
                    e[j] = ex2f(__uint_as_float(sreg[g * 8 + j]));
                    lacc += e[j];
                }
                uint32_t hq[4], lq[4];
                #pragma unroll
                for (int p = 0; p < 4; p++) {
                    uint32_t hp = pack_bf(e[2 * p + 1], e[2 * p]);
                    float h0 = __uint_as_float(hp << 16);
                    float h1 = __uint_as_float(hp & 0xFFFF0000u);
                    hq[p] = hp;
                    lq[p] = pack_bf(e[2 * p + 1] - h1, e[2 * p] - h0);
                }
                uint32_t off = cbase + ((kk0 + g * 16) ^ xorc);
                *(uint4*)(smem + SM_PH + off) = make_uint4(hq[0], hq[1], hq[2], hq[3]);
                *(uint4*)(smem + SM_PL + off) = make_uint4(lq[0], lq[1], lq[2], lq[3]);
            }
        } else {
            #pragma unroll
            for (int g = 0; g < 4; g++) {
                float e[8];
                #pragma unroll
                for (int j = 0; j < 8; j++) {
                    int col = c0 + g * 8 + j;
                    e[j] = (col < valid) ? ex2f(__uint_as_float(sreg[g * 8 + j])) : 0.f;
                    lacc += e[j];
                }
                uint32_t hq[4], lq[4];
                #pragma unroll
                for (int p = 0; p < 4; p++) {
                    uint32_t hp = pack_bf(e[2 * p + 1], e[2 * p]);
                    float h0 = __uint_as_float(hp << 16);
                    float h1 = __uint_as_float(hp & 0xFFFF0000u);
                    hq[p] = hp;
                    lq[p] = pack_bf(e[2 * p + 1] - h1, e[2 * p] - h0);
                }
                uint32_t off = cbase + ((kk0 + g * 16) ^ xorc);
                *(uint4*)(smem + SM_PH + off) = make_uint4(hq[0], hq[1], hq[2], hq[3]);
                *(uint4*)(smem + SM_PL + off) = make_uint4(lq[0], lq[1], lq[2], lq[3]);
            }
        }
    }
}
#endif  // __CUDA_ARCH_FEAT_SM103_ALL

__global__ void __launch_bounds__(256, 1) attn_kernel(
    const uint8_t* __restrict__ gq, const uint8_t* __restrict__ gk,
    const __nv_bfloat16* __restrict__ vh_t, const __nv_bfloat16* __restrict__ vl_t,
    float* __restrict__ ao)
{
    extern __shared__ __align__(1024) char smem[];
    const int tid = threadIdx.x;
    const int b = blockIdx.z, h = blockIdx.y;
    const size_t rowoff = (size_t)(b * H_ + h) * NN;
    const size_t vtoff = (size_t)(b * H_ + h) * HD_ * NN;
    const int q0 = blockIdx.x * 128;
    const int qvalid = min(128, NN - q0);

#if defined(__CUDA_ARCH_FEAT_SM103_ALL)
    const uint32_t sbase = smem_u32(smem);
    const int wid = tid >> 5;
    const int lane = tid & 31;
    const int half = wid >> 2;
    const int row = (wid & 3) * 32 + lane;
    const uint8_t* gk_rows = gk + rowoff * 128;

    if (wid == 0) TC_ALLOC(sbase + SM_TM, 512);
    if (tid == 0) { MB_INIT(sbase + SM_MBS, 1); MB_INIT(sbase + SM_MBO, 1); }
    __syncthreads();
    uint32_t tmem;
    asm volatile("ld.shared.b32 %0, [%1];" : "=r"(tmem) : "r"(sbase + SM_TM));

    load_rows_packed(smem + SM_Q, gq + (rowoff + q0) * 128, qvalid, tid);
    load_kv(smem, 0, gk_rows, vh_t, vl_t, vtoff, 0, 128, tid);
    load_kv(smem, 1, gk_rows, vh_t, vl_t, vtoff, 128, 128, tid);
    FENCE_ASYNC();
    __syncthreads();
    if (wid == 0 && elect1()) {
        issue_qk(sbase + SM_Q, sbase + SM_KV0, tmem + TM_S0);
        TC_COMMIT(sbase + SM_MBS);
    }

    uint32_t pS = 0, pO = 0;
    float lacc1 = 0.f, lacc2 = 0.f;

    for (int t = 0; t < NTALL; t++) {
        const int valid = (t < NT1) ? min(128, NKD - t * 128) : NKE_;
        mb_wait(sbase + SM_MBS, pS); pS ^= 1;
        TC_FENCE_AFTER();
        if (t + 1 < NTALL && wid == 0 && elect1()) {
            issue_qk(sbase + SM_Q, sbase + SM_KV0 + ((t + 1) & 3) * KV_STRIDE,
                     tmem + (((t + 1) & 1) ? TM_S1 : TM_S0));
            TC_COMMIT(sbase + SM_MBS);
        }
        if (t >= 1) { mb_wait(sbase + SM_MBO, pO); pO ^= 1; TC_FENCE_AFTER(); }
        if (t + 2 < NTALL) {
            int nb = (t + 2 < NT1) ? (t + 2) * 128 : NKD;
            int nv = (t + 2 < NT1) ? min(128, NKD - nb) : NKE_;
            load_kv(smem, (t + 2) & 3, gk_rows, vh_t, vl_t, vtoff, nb, nv, tid);
        }
        epilogue_tile(smem, tmem + ((t & 1) ? TM_S1 : TM_S0), row, half, valid,
                      (t < NT1) ? lacc1 : lacc2);
        TC_FENCE_BEFORE();
        FENCE_ASYNC();
        __syncthreads();
        if (wid == 0 && elect1()) {
            issue_pv(sbase + SM_PH,
                     sbase + SM_KV0 + (t & 3) * KV_STRIDE + KV_VOFF,
                     tmem + ((t < NT1) ? TM_O1 : TM_O2),
                     (t == 0) || (t == NT1));
            TC_COMMIT(sbase + SM_MBO);
        }
    }

    float* lsum1 = (float*)(smem + SM_LSUM1);
    float* lsum2 = (float*)(smem + SM_LSUM2);
    if (half == 1) { lsum1[row] = lacc1; lsum2[row] = lacc2; }
    __syncthreads();

    mb_wait(sbase + SM_MBO, pO); pO ^= 1;
    TC_FENCE_AFTER();
    if (half == 0) {
        float l1 = lacc1 + lsum1[row];
        float l2 = lacc2 + lsum2[row];
        uint32_t o1[32], o2[32];
        LDTM_X32(o1, tmem + TM_O1);
        LDTM_X32(o2, tmem + TM_O2);
        TC_WAIT_LD();
        float inv1 = 1.f / l1, inv2 = 1.f / l2;
        if (row < qvalid) {
            float* orow = ao + ((size_t)(b * NN + q0 + row)) * 256 + h * 32;
            #pragma unroll
            for (int d = 0; d < 32; d += 4) {
                float4 tv;
                tv.x = __uint_as_float(o1[d])     * inv1 + __uint_as_float(o2[d])     * inv2;
                tv.y = __uint_as_float(o1[d + 1]) * inv1 + __uint_as_float(o2[d + 1]) * inv2;
                tv.z = __uint_as_float(o1[d + 2]) * inv1 + __uint_as_float(o2[d + 2]) * inv2;
                tv.w = __uint_as_float(o1[d + 3]) * inv1 + __uint_as_float(o2[d + 3]) * inv2;
                *(float4*)(orow + d) = tv;
            }
        }
    }
    __syncthreads();
    if (wid == 0) {
        TC_RELINQ();
        TC_DEALLOC(tmem, 512);
    }
#else
    // scalar fallback
    const int qi = q0 + (tid & 127);
    const int hsel = tid >> 7;
    const bool active = qi < NN;

    float q[HD_];
    if (active) {
        const uint8_t* qr = gq + (rowoff + qi) * 128;
        #pragma unroll
        for (int d = 0; d < HD_; d++)
            q[d] = __bfloat162float(*(const __nv_bfloat16*)(qr + d * 2))
                 + __bfloat162float(*(const __nv_bfloat16*)(qr + 64 + d * 2));
    } else {
        #pragma unroll
        for (int d = 0; d < HD_; d++) q[d] = 0.f;
    }

    float o1[HD_] = {}, o2[HD_] = {};
    float l1 = 0.f, l2 = 0.f;
    const int ks = hsel ? 2048 : 0;
    const int ke = hsel ? NKD : 2048;
    if (active) {
        for (int j = ks; j < ke; j++) {
            const uint8_t* kr = gk + (rowoff + j) * 128;
            float s = 0.f;
            #pragma unroll
            for (int d = 0; d < HD_; d++)
                s += q[d] * (__bfloat162float(*(const __nv_bfloat16*)(kr + d * 2))
                           + __bfloat162float(*(const __nv_bfloat16*)(kr + 64 + d * 2)));
            float e = ex2f(s);
            l1 += e;
            #pragma unroll
            for (int d = 0; d < HD_; d++) {
                size_t vi = vtoff + (size_t)d * NN + j;
                o1[d] += e * (__bfloat162float(vh_t[vi]) + __bfloat162float(vl_t[vi]));
            }
        }
        if (hsel == 1) {
            for (int j = NKD; j < NN; j++) {
                const uint8_t* kr = gk + (rowoff + j) * 128;
                float s = 0.f;
                #pragma unroll
                for (int d = 0; d < HD_; d++)
                    s += q[d] * (__bfloat162float(*(const __nv_bfloat16*)(kr + d * 2))
                               + __bfloat162float(*(const __nv_bfloat16*)(kr + 64 + d * 2)));
                float e = ex2f(s);
                l2 += e;
                #pragma unroll
                for (int d = 0; d < HD_; d++) {
                    size_t vi = vtoff + (size_t)d * NN + j;
                    o2[d] += e * (__bfloat162float(vh_t[vi]) + __bfloat162float(vl_t[vi]));
                }
            }
        }
    }
    float* sh = (float*)smem;
    float* shl = sh + 128 * HD_;
    float* sh2 = shl + 128;
    float* sh2l = sh2 + 128 * HD_;
    if (hsel == 1) {
        int r = tid & 127;
        #pragma unroll
        for (int d = 0; d < HD_; d++) { sh[r * HD_ + d] = o1[d]; sh2[r * HD_ + d] = o2[d]; }
        shl[r] = l1; sh2l[r] = l2;
    }
    __syncthreads();
    if (hsel == 0 && active) {
        int r = tid & 127;
        float lt = l1 + shl[r];
        float inv1 = 1.f / lt;
        float inv2 = 1.f / sh2l[r];
        float* orow = ao + ((size_t)(b * NN + qi)) * 256 + h * HD_;
        #pragma unroll
        for (int d = 0; d < HD_; d++)
            orow[d] = (o1[d] + sh[r * HD_ + d]) * inv1 + sh2[r * HD_ + d] * inv2;
    }
#endif
}

// ---------------- launch ----------------
extern "C" void kernel_launch(void* const* d_in, const int* in_sizes, int n_in,
                              void* d_out, int out_size)
{
    const float* q    = (const float*)d_in[0];
    const float* k    = (const float*)d_in[1];
    const float* v    = (const float*)d_in[2];
    const float* fimg = (const float*)d_in[3];
    const float* ftxt = (const float*)d_in[4];
    const float* Wq   = (const float*)d_in[5];
    const float* bq   = (const float*)d_in[6];
    const float* Wk   = (const float*)d_in[7];
    const float* bk   = (const float*)d_in[8];
    const float* Wv   = (const float*)d_in[9];
    const float* bv   = (const float*)d_in[10];
    const float* Wo   = (const float*)d_in[11];
    const float* bo   = (const float*)d_in[12];
    float* out = (float*)d_out;

    uint8_t *gq, *gk;
    __nv_bfloat16 *gvh, *gvl;
    float* ao;
    cudaGetSymbolAddress((void**)&gq, g_q);
    cudaGetSymbolAddress((void**)&gk, g_k);
    cudaGetSymbolAddress((void**)&gvh, g_vh);
    cudaGetSymbolAddress((void**)&gvl, g_vl);
    cudaGetSymbolAddress((void**)&ao, g_ao);

    cudaFuncSetAttribute(gemm_tc, cudaFuncAttributeMaxDynamicSharedMemorySize, GS_TOTAL);
    cudaFuncSetAttribute(attn_kernel, cudaFuncAttributeMaxDynamicSharedMemorySize, SMEM_TOTAL);

    gemm_tc<<<dim3(MT, 3), 256, GS_TOTAL>>>(
        q, k, v, Wq, Wk, Wv, bq, bk, bv,
        gq, gk, gvh, gvl, nullptr, 1, fimg, ftxt);

    dim3 ga(33, H_, BB);
    attn_kernel<<<ga, 256, SMEM_TOTAL>>>(gq, gk, gvh, gvl, ao);

    gemm_tc<<<dim3(MT, 1), 256, GS_TOTAL>>>(
        ao, nullptr, nullptr, Wo, nullptr, nullptr, bo, nullptr, nullptr,
        gq, gk, gvh, gvl, out, 0, fimg, ftxt);
}

// round 14
// speedup vs baseline: 2.4925x; 1.1480x over previous
#include <cuda_runtime.h>
#include <cuda_bf16.h>
#include <stdint.h>
#include <math.h>

#define D_    256
#define H_    8
#define HD_   32
#define NIMG_ 4096
#define NN    4112
#define BB    2
#define NKE_  64
#define MROWS (BB * NN)      /* 8224 */
#define NKD   (NN - NKE_)    /* 4048 */
#define NT1   32             /* ceil(4048/128) */
#define NTALL 33             /* 32 dense tiles + 1 mem tile */
#define MT    65             /* ceil(8224/128) GEMM row tiles */

// ---------------- global scratch (no allocs allowed) ----------------
// Q/K packed: per (b,h,n) one 128B row: hi bf16 d0..31 at [0,64), lo at [64,128)
__device__ uint8_t g_q[(size_t)BB * H_ * NN * 128];
__device__ uint8_t g_k[(size_t)BB * H_ * NN * 128];
// V transposed: [b][h][d][key], hi and lo arrays
__device__ __nv_bfloat16 g_vh[(size_t)BB * H_ * HD_ * NN];
__device__ __nv_bfloat16 g_vl[(size_t)BB * H_ * HD_ * NN];
__device__ float g_ao[(size_t)MROWS * D_];

// scale: 1/sqrt(32) * log2(e)  (so softmax exp == exp2)
#define QSCALE (0.17677669529663687f * 1.4426950408889634f)

// idesc kind::f16: dtypeF32(1<<4) | aBF16(1<<7) | bBF16(1<<10) | (N/8)<<17 | (M/16)<<24
#define IDESC_128 0x8200490u  /* M=128 N=128 */
#define IDESC_PV  0x8080490u  /* M=128 N=32  */

// ---------------- arch-portable helpers ----------------
__device__ __forceinline__ uint32_t smem_u32(const void* p) {
    uint32_t a;
    asm("{ .reg .u64 t; cvta.to.shared.u64 t, %1; cvt.u32.u64 %0, t; }" : "=r"(a) : "l"(p));
    return a;
}
__device__ __forceinline__ float ex2f(float x) {
    float y; asm("ex2.approx.ftz.f32 %0, %1;" : "=f"(y) : "f"(x)); return y;
}
__device__ __forceinline__ uint32_t swz(uint32_t b) { return b ^ ((b >> 3) & 0x70); }
__device__ __forceinline__ uint32_t pack_bf(float hi, float lo) {
    uint32_t r; asm("cvt.rn.bf16x2.f32 %0, %1, %2;" : "=r"(r) : "f"(hi), "f"(lo)); return r;
}

// ---------------- tcgen05 helpers: sm_103a ONLY ----------------
#if defined(__CUDA_ARCH_FEAT_SM103_ALL)
__device__ __forceinline__ bool elect1() {
    uint32_t p;
    asm volatile("{ .reg .pred p; elect.sync _|p, 0xFFFFFFFF; selp.b32 %0, 1, 0, p; }" : "=r"(p));
    return p != 0;
}
__device__ __forceinline__ uint64_t mkdesc(uint32_t addr) {
    return ((uint64_t)2 << 61) | ((uint64_t)1 << 46) | ((uint64_t)64 << 32)
         | ((uint64_t)1 << 16) | ((addr >> 4) & 0x3FFF);
}
__device__ __forceinline__ void mma_ss(uint32_t d, uint64_t a, uint64_t b, uint32_t idesc, bool acc) {
    uint32_t en = acc ? 1u : 0u;
    asm volatile(
        "{\n\t.reg .pred p;\n\tsetp.ne.u32 p, %5, 0;\n\t"
        "tcgen05.mma.cta_group::1.kind::f16 [%0], %1, %2, %3, {%4,%4,%4,%4}, p;\n\t}"
        :: "r"(d), "l"(a), "l"(b), "r"(idesc), "r"(0u), "r"(en) : "memory");
}
#define TC_COMMIT(mbar) \
    asm volatile("tcgen05.commit.cta_group::1.mbarrier::arrive::one.shared::cluster.b64 [%0];" :: "r"(mbar) : "memory")
#define TC_ALLOC(smem_addr, n) \
    asm volatile("tcgen05.alloc.cta_group::1.sync.aligned.shared::cta.b32 [%0], %1;" :: "r"(smem_addr), "r"(n) : "memory")
#define TC_DEALLOC(tmem, n) \
    asm volatile("tcgen05.dealloc.cta_group::1.sync.aligned.b32 %0, %1;" :: "r"(tmem), "r"(n))
#define TC_RELINQ() asm volatile("tcgen05.relinquish_alloc_permit.cta_group::1.sync.aligned;")
#define TC_WAIT_LD() asm volatile("tcgen05.wait::ld.sync.aligned;" ::: "memory")
#define TC_FENCE_AFTER() asm volatile("tcgen05.fence::after_thread_sync;" ::: "memory")
#define TC_FENCE_BEFORE() asm volatile("tcgen05.fence::before_thread_sync;" ::: "memory")
#define FENCE_ASYNC() asm volatile("fence.proxy.async.shared::cta;" ::: "memory")
#define MB_INIT(addr, cnt) \
    asm volatile("mbarrier.init.shared.b64 [%0], %1;" :: "r"(addr), "r"(cnt) : "memory")

__device__ __forceinline__ void mb_wait(uint32_t mbar, uint32_t parity) {
    uint32_t done;
    asm volatile(
        "{\n\t.reg .pred p;\n\t"
        "mbarrier.try_wait.parity.acquire.cta.shared::cta.b64 p, [%1], %2;\n\t"
        "selp.b32 %0, 1, 0, p;\n\t}"
        : "=r"(done) : "r"(mbar), "r"(parity) : "memory");
    if (!done) {
        asm volatile(
            "{\n\t.reg .pred P1;\n\t"
            "WL_%=:\n\t"
            "mbarrier.try_wait.parity.acquire.cta.shared::cta.b64 P1, [%0], %1, 0x989680;\n\t"
            "@P1 bra.uni WD_%=;\n\t"
            "bra.uni WL_%=;\n\t"
            "WD_%=:\n\t}"
            :: "r"(mbar), "r"(parity) : "memory");
    }
}

#define LDTM_X32(r, addr) \
    asm volatile( \
        "tcgen05.ld.sync.aligned.32x32b.x32.b32 " \
        "{%0,%1,%2,%3,%4,%5,%6,%7,%8,%9,%10,%11,%12,%13,%14,%15," \
        "%16,%17,%18,%19,%20,%21,%22,%23,%24,%25,%26,%27,%28,%29,%30,%31}, [%32];" \
        : "=r"((r)[0]),"=r"((r)[1]),"=r"((r)[2]),"=r"((r)[3]),"=r"((r)[4]),"=r"((r)[5]), \
          "=r"((r)[6]),"=r"((r)[7]),"=r"((r)[8]),"=r"((r)[9]),"=r"((r)[10]),"=r"((r)[11]), \
          "=r"((r)[12]),"=r"((r)[13]),"=r"((r)[14]),"=r"((r)[15]),"=r"((r)[16]),"=r"((r)[17]), \
          "=r"((r)[18]),"=r"((r)[19]),"=r"((r)[20]),"=r"((r)[21]),"=r"((r)[22]),"=r"((r)[23]), \
          "=r"((r)[24]),"=r"((r)[25]),"=r"((r)[26]),"=r"((r)[27]),"=r"((r)[28]),"=r"((r)[29]), \
          "=r"((r)[30]),"=r"((r)[31]) : "r"(addr))
#endif  // __CUDA_ARCH_FEAT_SM103_ALL

// ================= tcgen05 projection GEMM (single-buffer, 2 CTAs/SM) =================
// C[m,j] = sum_i A[m,i]*W[j,i] + bias[j]; M tile 128/CTA; K=256 in 4 chunks of 64.
// 3-term bf16 hi/lo emulation. modes: 0 fp32 out; 1 Q(rope+QSCALE->packed);
// 2 K(rope->packed); 3 V(transposed hi/lo).
// Freqs loaded per-thread from global in the epilogue (no SMEM staging) so that
// GS_TOTAL*2 fits in one SM -> 2 resident CTAs overlap each other's latency.
#define GS_AH   0        /* 16384 */
#define GS_AL   16384    /* 16384 */
#define GS_WH   32768    /* 32768 */
#define GS_WL   65536    /* 32768 */
#define GS_BIAS 98304    /* 1024 */
#define GS_TM   99328
#define GS_MB   99336
#define GS_TOTAL 99456

__global__ void __launch_bounds__(256, 2) gemm_tc(
    const float* __restrict__ A0, const float* __restrict__ A1, const float* __restrict__ A2,
    const float* __restrict__ W0, const float* __restrict__ W1, const float* __restrict__ W2,
    const float* __restrict__ B0, const float* __restrict__ B1, const float* __restrict__ B2,
    uint8_t* __restrict__ gq, uint8_t* __restrict__ gk,
    __nv_bfloat16* __restrict__ gvh, __nv_bfloat16* __restrict__ gvl,
    float* __restrict__ outf, int qkv,
    const float* __restrict__ fimg, const float* __restrict__ ftxt)
{
    extern __shared__ __align__(1024) char smem[];
    const int tid = threadIdx.x;
    const int m0 = blockIdx.x * 128;
    int mode;
    const float *A, *W, *bias;
    if (qkv) {
        mode = blockIdx.y + 1;
        if (blockIdx.y == 0)      { A = A0; W = W0; bias = B0; }
        else if (blockIdx.y == 1) { A = A1; W = W1; bias = B1; }
        else                      { A = A2; W = W2; bias = B2; }
    } else { mode = 0; A = A0; W = W0; bias = B0; }

#if defined(__CUDA_ARCH_FEAT_SM103_ALL)
    const uint32_t sb = smem_u32(smem);
    const int wid = tid >> 5;
    const int lane = tid & 31;

    if (wid == 0) TC_ALLOC(sb + GS_TM, 256);
    if (tid == 0) MB_INIT(sb + GS_MB, 1);
    __syncthreads();
    uint32_t tmem;
    asm volatile("ld.shared.b32 %0, [%1];" : "=r"(tmem) : "r"(sb + GS_TM));

    // stage bias
    if (tid < 256) *(float*)(smem + GS_BIAS + tid * 4) = bias[tid];

    uint32_t par = 0;
    for (int c = 0; c < 4; c++) {
        if (c > 0) { mb_wait(sb + GS_MB, par); par ^= 1; }
        const int k0 = c * 64;
        // load A chunk: 128 rows x 64 floats -> hi/lo bf16
        #pragma unroll
        for (int it = 0; it < 8; it++) {
            int i = tid + it * 256;
            int r = i >> 4;
            int c4 = (i & 15) * 4;
            float4 va = make_float4(0.f, 0.f, 0.f, 0.f);
            if (m0 + r < MROWS) va = *(const float4*)(A + (size_t)(m0 + r) * 256 + k0 + c4);
            uint32_t h01 = pack_bf(va.y, va.x);
            uint32_t h23 = pack_bf(va.w, va.z);
            float hx = __uint_as_float(h01 << 16), hy = __uint_as_float(h01 & 0xFFFF0000u);
            float hz = __uint_as_float(h23 << 16), hw = __uint_as_float(h23 & 0xFFFF0000u);
            uint32_t l01 = pack_bf(va.y - hy, va.x - hx);
            uint32_t l23 = pack_bf(va.w - hw, va.z - hz);
            uint32_t off = swz((uint32_t)(r * 128 + c4 * 2));
            *(uint2*)(smem + GS_AH + off) = make_uint2(h01, h23);
            *(uint2*)(smem + GS_AL + off) = make_uint2(l01, l23);
        }
        // load W chunk: 256 rows x 64 floats
        #pragma unroll
        for (int it = 0; it < 16; it++) {
            int i = tid + it * 256;
            int r = i >> 4;
            int c4 = (i & 15) * 4;
            float4 vw = *(const float4*)(W + (size_t)r * 256 + k0 + c4);
            uint32_t h01 = pack_bf(vw.y, vw.x);
            uint32_t h23 = pack_bf(vw.w, vw.z);
            float hx = __uint_as_float(h01 << 16), hy = __uint_as_float(h01 & 0xFFFF0000u);
            float hz = __uint_as_float(h23 << 16), hw = __uint_as_float(h23 & 0xFFFF0000u);
            uint32_t l01 = pack_bf(vw.y - hy, vw.x - hx);
            uint32_t l23 = pack_bf(vw.w - hw, vw.z - hz);
            uint32_t off = swz((uint32_t)(r * 128 + c4 * 2));
            *(uint2*)(smem + GS_WH + off) = make_uint2(h01, h23);
            *(uint2*)(smem + GS_WL + off) = make_uint2(l01, l23);
        }
        FENCE_ASYNC();
        __syncthreads();
        if (wid == 0 && elect1()) {
            uint64_t ah = mkdesc(sb + GS_AH), al = mkdesc(sb + GS_AL);
            uint64_t wh = mkdesc(sb + GS_WH), wl = mkdesc(sb + GS_WL);
            #pragma unroll
            for (int nh = 0; nh < 2; nh++) {
                uint32_t dcol = tmem + nh * 128;
                uint64_t bo = (uint64_t)nh * 1024;
                #pragma unroll
                for (int ks = 0; ks < 4; ks++) {
                    uint64_t a_h = ah + 2 * ks, a_l = al + 2 * ks;
                    uint64_t b_h = wh + bo + 2 * ks, b_l = wl + bo + 2 * ks;
                    mma_ss(dcol, a_h, b_h, IDESC_128, !(c == 0 && ks == 0));
                    mma_ss(dcol, a_h, b_l, IDESC_128, true);
                    mma_ss(dcol, a_l, b_h, IDESC_128, true);
                }
            }
            TC_COMMIT(sb + GS_MB);
        }
    }
    mb_wait(sb + GS_MB, par);
    TC_FENCE_AFTER();

    // epilogue: warp w -> rows (w&3)*32+lane, cols (w>>2)*128 + cc*32
    {
        const int r = (wid & 3) * 32 + lane;
        const int m = m0 + r;
        const int cb0 = (wid >> 2) * 128;
        const bool mok = (m < MROWS);
        int bb = (m >= NN) ? 1 : 0;
        int n = m - bb * NN;
        // per-thread freq registers (modes 1,2): 16 contiguous float2 at row n
        float2 fr[16];
        if (mok && (mode == 1 || mode == 2)) {
            const float* fbase = (n < NIMG_) ? (fimg + (size_t)n * 32)
                                             : (ftxt + (size_t)(n - NIMG_) * 32);
            #pragma unroll
            for (int i = 0; i < 8; i++) {
                float4 t = *(const float4*)(fbase + i * 4);
                fr[2 * i]     = make_float2(t.x, t.y);
                fr[2 * i + 1] = make_float2(t.z, t.w);
            }
        }
        #pragma unroll
        for (int cc = 0; cc < 4; cc++) {
            const int c0 = cb0 + cc * 32;
            uint32_t s[32];
            LDTM_X32(s, tmem + c0);
            TC_WAIT_LD();
            if (!mok) continue;
            if (mode == 0) {
                #pragma unroll
                for (int j = 0; j < 32; j++) {
                    float bv = *(const float*)(smem + GS_BIAS + (c0 + j) * 4);
                    outf[(size_t)m * 256 + c0 + j] = __uint_as_float(s[j]) + bv;
                }
            } else if (mode == 3) {
                const int head = c0 >> 5;
                #pragma unroll
                for (int j = 0; j < 32; j++) {
                    float bv = *(const float*)(smem + GS_BIAS + (c0 + j) * 4);
                    float val = __uint_as_float(s[j]) + bv;
                    __nv_bfloat16 hb = __float2bfloat16(val);
                    float rr = val - __bfloat162float(hb);
                    size_t dst = ((size_t)(bb * H_ + head) * HD_ + j) * NN + n;
                    gvh[dst] = hb;
                    gvl[dst] = __float2bfloat16(rr);
                }
            } else {
                const int head = c0 >> 5;
                uint8_t* gout = (mode == 1) ? gq : gk;
                uint8_t* rowp = gout + ((size_t)(bb * H_ + head) * NN + n) * 128;
                #pragma unroll
                for (int p = 0; p < 16; p++) {
                    float b0v = *(const float*)(smem + GS_BIAS + (c0 + 2 * p) * 4);
                    float b1v = *(const float*)(smem + GS_BIAS + (c0 + 2 * p + 1) * 4);
                    float x0 = __uint_as_float(s[2 * p]) + b0v;
                    float x1 = __uint_as_float(s[2 * p + 1]) + b1v;
                    float y0 = x0 * fr[p].x - x1 * fr[p].y;
                    float y1 = x0 * fr[p].y + x1 * fr[p].x;
                    if (mode == 1) { y0 *= QSCALE; y1 *= QSCALE; }
                    uint32_t hp = pack_bf(y1, y0);
                    float h0 = __uint_as_float(hp << 16);
                    float h1 = __uint_as_float(hp & 0xFFFF0000u);
                    uint32_t lp = pack_bf(y1 - h1, y0 - h0);
                    *(uint32_t*)(rowp + p * 4) = hp;
                    *(uint32_t*)(rowp + 64 + p * 4) = lp;
                }
            }
        }
    }
    __syncthreads();
    if (wid == 0) {
        TC_RELINQ();
        TC_DEALLOC(tmem, 256);
    }
#else
    // naive fallback (only if sm_103a cubin absent)
    for (int idx = tid; idx < 128 * 128; idx += 256) {
        int r = idx >> 7;
        int p = idx & 127;
        int m = m0 + r;
        if (m >= MROWS) continue;
        int j0_ = p * 2;
        float s0 = bias[j0_], s1 = bias[j0_ + 1];
        for (int k2 = 0; k2 < 256; k2++) {
            float a = A[(size_t)m * 256 + k2];
            s0 += a * W[(size_t)j0_ * 256 + k2];
            s1 += a * W[(size_t)(j0_ + 1) * 256 + k2];
        }
        int bb = (m >= NN) ? 1 : 0;
        int n = m - bb * NN;
        if (mode == 1 || mode == 2) {
            int cidx = (j0_ & 31) >> 1;
            const float* f = (n < NIMG_) ? (fimg + ((size_t)n * 16 + cidx) * 2)
                                         : (ftxt + ((size_t)(n - NIMG_) * 16 + cidx) * 2);
            float y0 = s0 * f[0] - s1 * f[1];
            float y1 = s0 * f[1] + s1 * f[0];
            if (mode == 1) { y0 *= QSCALE; y1 *= QSCALE; }
            int head = j0_ >> 5, d = j0_ & 31;
            uint8_t* gout = (mode == 1) ? gq : gk;
            uint8_t* rowp = gout + ((size_t)(bb * H_ + head) * NN + n) * 128;
            uint32_t hp = pack_bf(y1, y0);
            float h0 = __uint_as_float(hp << 16), h1 = __uint_as_float(hp & 0xFFFF0000u);
            uint32_t lp = pack_bf(y1 - h1, y0 - h0);
            *(uint32_t*)(rowp + (d >> 1) * 4) = hp;
            *(uint32_t*)(rowp + 64 + (d >> 1) * 4) = lp;
        } else if (mode == 3) {
            int head = j0_ >> 5, d = j0_ & 31;
            #pragma unroll
            for (int e = 0; e < 2; e++) {
                float val = e ? s1 : s0;
                __nv_bfloat16 hb = __float2bfloat16(val);
                size_t dst = ((size_t)(bb * H_ + head) * HD_ + d + e) * NN + n;
                gvh[dst] = hb;
                gvl[dst] = __float2bfloat16(val - __bfloat162float(hb));
            }
        } else {
            outf[(size_t)m * 256 + j0_] = s0;
            outf[(size_t)m * 256 + j0_ + 1] = s1;
        }
    }
#endif
}

// ================= attention (FROZEN: R11-passing version) =================
#define SM_Q     0
#define SM_KV0   16384
#define KV_STRIDE 32768
#define KV_VOFF  16384
#define SM_PH    147456
#define SM_PL    180224
#define SM_TM    212992
#define SM_MBS   213000
#define SM_MBO   213008
#define SM_LSUM1 213056
#define SM_LSUM2 213568
#define SMEM_TOTAL 214080

#define TM_S0 0
#define TM_S1 128
#define TM_O1 256
#define TM_O2 288

#if defined(__CUDA_ARCH_FEAT_SM103_ALL)
__device__ __forceinline__ void load_rows_packed(
    char* dst, const uint8_t* gpk, int valid, int tid)
{
    #pragma unroll
    for (int it = 0; it < 4; it++) {
        int f = tid + it * 256;
        int r = f >> 3;
        int cb = (f & 7) * 16;
        uint4 x = make_uint4(0, 0, 0, 0);
        if (r < valid) x = *(const uint4*)(gpk + (size_t)r * 128 + cb);
        *(uint4*)(dst + swz((uint32_t)(r * 128 + cb))) = x;
    }
}

__device__ __forceinline__ void load_vt(
    char* dst, const __nv_bfloat16* gvh_t, const __nv_bfloat16* gvl_t,
    int valid, int tid)
{
    #pragma unroll
    for (int it = 0; it < 2; it++) {
        int c = tid + it * 256;
        int d = c >> 4;
        int kc = c & 15;
        uint4 xh = make_uint4(0, 0, 0, 0), xl = make_uint4(0, 0, 0, 0);
        if (kc * 8 < valid) {
            xh = *(const uint4*)(gvh_t + (size_t)d * NN + kc * 8);
            xl = *(const uint4*)(gvl_t + (size_t)d * NN + kc * 8);
        }
        uint32_t off = swz((uint32_t)((d >> 3) * 1024 + (kc >> 3) * 4096
                                      + (d & 7) * 128 + (kc & 7) * 16));
        *(uint4*)(dst + off) = xh;
        *(uint4*)(dst + 8192 + off) = xl;
    }
}

__device__ __forceinline__ void load_kv(
    char* smem, int buf, const uint8_t* gk_rows,
    const __nv_bfloat16* vh_t, const __nv_bfloat16* vl_t,
    size_t vtoff, int kbase, int valid, int tid)
{
    char* kb = smem + SM_KV0 + buf * KV_STRIDE;
    load_rows_packed(kb, gk_rows + (size_t)kbase * 128, valid, tid);
    load_vt(kb + KV_VOFF, vh_t + vtoff + kbase, vl_t + vtoff + kbase, valid, tid);
}

__device__ __forceinline__ void issue_qk(uint32_t qb, uint32_t kb, uint32_t tmem_d) {
    uint64_t qd = mkdesc(qb);
    uint64_t kd = mkdesc(kb);
    mma_ss(tmem_d, qd + 0, kd + 0, IDESC_128, false);
    mma_ss(tmem_d, qd + 2, kd + 2, IDESC_128, true);
    mma_ss(tmem_d, qd + 0, kd + 4, IDESC_128, true);
    mma_ss(tmem_d, qd + 2, kd + 6, IDESC_128, true);
    mma_ss(tmem_d, qd + 4, kd + 0, IDESC_128, true);
    mma_ss(tmem_d, qd + 6, kd + 2, IDESC_128, true);
}

__device__ __forceinline__ void issue_pv(uint32_t phb, uint32_t vb, uint32_t tmem_d, bool first) {
    uint64_t aph = mkdesc(phb);
    uint64_t apl = mkdesc(phb + 32768);
    uint64_t bvh = mkdesc(vb);
    uint64_t bvl = mkdesc(vb + 8192);
    #pragma unroll
    for (int term = 0; term < 3; term++) {
        uint64_t Aa = (term == 2) ? apl : aph;
        uint64_t Bb = (term == 1) ? bvl : bvh;
        #pragma unroll
        for (int ks = 0; ks < 8; ks++) {
            uint64_t ad = Aa + (ks < 4 ? 2 * ks : 1024 + 2 * (ks - 4));
            uint64_t bd = Bb + (ks < 4 ? 2 * ks : 256 + 2 * (ks - 4));
            mma_ss(tmem_d, ad, bd, IDESC_PV, !(first && term == 0 && ks == 0));
        }
    }
}

// Softmax epilogue with STS.128 P writes (8 cols per store, conflict-phased clean).
__device__ __forceinline__ void epilogue_tile(
    char* smem, uint32_t tmem_s, int row, int half, int valid, float& lacc)
{
    const uint32_t xorc = (uint32_t)((row & 7) << 4);
    const uint32_t base0 = (uint32_t)((row >> 3) * 1024 + (row & 7) * 128);
    #pragma unroll
    for (int cc = 0; cc < 2; cc++) {
        const int c0 = half * 64 + cc * 32;
        uint32_t sreg[32];
        LDTM_X32(sreg, tmem_s + c0);
        TC_WAIT_LD();
        const uint32_t cbase = base0 + (uint32_t)((c0 >> 6) * 16384);
        const uint32_t kk0 = (uint32_t)((c0 & 63) * 2);
        if (valid >= c0 + 32) {
            #pragma unroll
            for (int g = 0; g < 4; g++) {
                float e[8];
                #pragma unroll
                for (int j = 0; j < 8; j++) {
                    e[j] = ex2f(__uint_as_float(sreg[g * 8 + j]));
                    lacc += e[j];
                }
                uint32_t hq[4], lq[4];
                #pragma unroll
                for (int p = 0; p < 4; p++) {
                    uint32_t hp = pack_bf(e[2 * p + 1], e[2 * p]);
                    float h0 = __uint_as_float(hp << 16);
                    float h1 = __uint_as_float(hp & 0xFFFF0000u);
                    hq[p] = hp;
                    lq[p] = pack_bf(e[2 * p + 1] - h1, e[2 * p] - h0);
                }
                uint32_t off = cbase + ((kk0 + g * 16) ^ xorc);
                *(uint4*)(smem + SM_PH + off) = make_uint4(hq[0], hq[1], hq[2], hq[3]);
                *(uint4*)(smem + SM_PL + off) = make_uint4(lq[0], lq[1], lq[2], lq[3]);
            }
        } else {
            #pragma unroll
            for (int g = 0; g < 4; g++) {
                float e[8];
                #pragma unroll
                for (int j = 0; j < 8; j++) {
                    int col = c0 + g * 8 + j;
                    e[j] = (col < valid) ? ex2f(__uint_as_float(sreg[g * 8 + j])) : 0.f;
                    lacc += e[j];
                }
                uint32_t hq[4], lq[4];
                #pragma unroll
                for (int p = 0; p < 4; p++) {
                    uint32_t hp = pack_bf(e[2 * p + 1], e[2 * p]);
                    float h0 = __uint_as_float(hp << 16);
                    float h1 = __uint_as_float(hp & 0xFFFF0000u);
                    hq[p] = hp;
                    lq[p] = pack_bf(e[2 * p + 1] - h1, e[2 * p] - h0);
                }
                uint32_t off = cbase + ((kk0 + g * 16) ^ xorc);
                *(uint4*)(smem + SM_PH + off) = make_uint4(hq[0], hq[1], hq[2], hq[3]);
                *(uint4*)(smem + SM_PL + off) = make_uint4(lq[0], lq[1], lq[2], lq[3]);
            }
        }
    }
}
#endif  // __CUDA_ARCH_FEAT_SM103_ALL

__global__ void __launch_bounds__(256, 1) attn_kernel(
    const uint8_t* __restrict__ gq, const uint8_t* __restrict__ gk,
    const __nv_bfloat16* __restrict__ vh_t, const __nv_bfloat16* __restrict__ vl_t,
    float* __restrict__ ao)
{
    extern __shared__ __align__(1024) char smem[];
    const int tid = threadIdx.x;
    const int b = blockIdx.z, h = blockIdx.y;
    const size_t rowoff = (size_t)(b * H_ + h) * NN;
    const size_t vtoff = (size_t)(b * H_ + h) * HD_ * NN;
    const int q0 = blockIdx.x * 128;
    const int qvalid = min(128, NN - q0);

#if defined(__CUDA_ARCH_FEAT_SM103_ALL)
    const uint32_t sbase = smem_u32(smem);
    const int wid = tid >> 5;
    const int lane = tid & 31;
    const int half = wid >> 2;
    const int row = (wid & 3) * 32 + lane;
    const uint8_t* gk_rows = gk + rowoff * 128;

    if (wid == 0) TC_ALLOC(sbase + SM_TM, 512);
    if (tid == 0) { MB_INIT(sbase + SM_MBS, 1); MB_INIT(sbase + SM_MBO, 1); }
    __syncthreads();
    uint32_t tmem;
    asm volatile("ld.shared.b32 %0, [%1];" : "=r"(tmem) : "r"(sbase + SM_TM));

    load_rows_packed(smem + SM_Q, gq + (rowoff + q0) * 128, qvalid, tid);
    load_kv(smem, 0, gk_rows, vh_t, vl_t, vtoff, 0, 128, tid);
    load_kv(smem, 1, gk_rows, vh_t, vl_t, vtoff, 128, 128, tid);
    FENCE_ASYNC();
    __syncthreads();
    if (wid == 0 && elect1()) {
        issue_qk(sbase + SM_Q, sbase + SM_KV0, tmem + TM_S0);
        TC_COMMIT(sbase + SM_MBS);
    }

    uint32_t pS = 0, pO = 0;
    float lacc1 = 0.f, lacc2 = 0.f;

    for (int t = 0; t < NTALL; t++) {
        const int valid = (t < NT1) ? min(128, NKD - t * 128) : NKE_;
        mb_wait(sbase + SM_MBS, pS); pS ^= 1;
        TC_FENCE_AFTER();
        if (t + 1 < NTALL && wid == 0 && elect1()) {
            issue_qk(sbase + SM_Q, sbase + SM_KV0 + ((t + 1) & 3) * KV_STRIDE,
                     tmem + (((t + 1) & 1) ? TM_S1 : TM_S0));
            TC_COMMIT(sbase + SM_MBS);
        }
        if (t >= 1) { mb_wait(sbase + SM_MBO, pO); pO ^= 1; TC_FENCE_AFTER(); }
        if (t + 2 < NTALL) {
            int nb = (t + 2 < NT1) ? (t + 2) * 128 : NKD;
            int nv = (t + 2 < NT1) ? min(128, NKD - nb) : NKE_;
            load_kv(smem, (t + 2) & 3, gk_rows, vh_t, vl_t, vtoff, nb, nv, tid);
        }
        epilogue_tile(smem, tmem + ((t & 1) ? TM_S1 : TM_S0), row, half, valid,
                      (t < NT1) ? lacc1 : lacc2);
        TC_FENCE_BEFORE();
        FENCE_ASYNC();
        __syncthreads();
        if (wid == 0 && elect1()) {
            issue_pv(sbase + SM_PH,
                     sbase + SM_KV0 + (t & 3) * KV_STRIDE + KV_VOFF,
                     tmem + ((t < NT1) ? TM_O1 : TM_O2),
                     (t == 0) || (t == NT1));
            TC_COMMIT(sbase + SM_MBO);
        }
    }

    float* lsum1 = (float*)(smem + SM_LSUM1);
    float* lsum2 = (float*)(smem + SM_LSUM2);
    if (half == 1) { lsum1[row] = lacc1; lsum2[row] = lacc2; }
    __syncthreads();

    mb_wait(sbase + SM_MBO, pO); pO ^= 1;
    TC_FENCE_AFTER();
    if (half == 0) {
        float l1 = lacc1 + lsum1[row];
        float l2 = lacc2 + lsum2[row];
        uint32_t o1[32], o2[32];
        LDTM_X32(o1, tmem + TM_O1);
        LDTM_X32(o2, tmem + TM_O2);
        TC_WAIT_LD();
        float inv1 = 1.f / l1, inv2 = 1.f / l2;
        if (row < qvalid) {
            float* orow = ao + ((size_t)(b * NN + q0 + row)) * 256 + h * 32;
            #pragma unroll
            for (int d = 0; d < 32; d += 4) {
                float4 tv;
                tv.x = __uint_as_float(o1[d])     * inv1 + __uint_as_float(o2[d])     * inv2;
                tv.y = __uint_as_float(o1[d + 1]) * inv1 + __uint_as_float(o2[d + 1]) * inv2;
                tv.z = __uint_as_float(o1[d + 2]) * inv1 + __uint_as_float(o2[d + 2]) * inv2;
                tv.w = __uint_as_float(o1[d + 3]) * inv1 + __uint_as_float(o2[d + 3]) * inv2;
                *(float4*)(orow + d) = tv;
            }
        }
    }
    __syncthreads();
    if (wid == 0) {
        TC_RELINQ();
        TC_DEALLOC(tmem, 512);
    }
#else
    // scalar fallback
    const int qi = q0 + (tid & 127);
    const int hsel = tid >> 7;
    const bool active = qi < NN;

    float q[HD_];
    if (active) {
        const uint8_t* qr = gq + (rowoff + qi) * 128;
        #pragma unroll
        for (int d = 0; d < HD_; d++)
            q[d] = __bfloat162float(*(const __nv_bfloat16*)(qr + d * 2))
                 + __bfloat162float(*(const __nv_bfloat16*)(qr + 64 + d * 2));
    } else {
        #pragma unroll
        for (int d = 0; d < HD_; d++) q[d] = 0.f;
    }

    float o1[HD_] = {}, o2[HD_] = {};
    float l1 = 0.f, l2 = 0.f;
    const int ks = hsel ? 2048 : 0;
    const int ke = hsel ? NKD : 2048;
    if (active) {
        for (int j = ks; j < ke; j++) {
            const uint8_t* kr = gk + (rowoff + j) * 128;
            float s = 0.f;
            #pragma unroll
            for (int d = 0; d < HD_; d++)
                s += q[d] * (__bfloat162float(*(const __nv_bfloat16*)(kr + d * 2))
                           + __bfloat162float(*(const __nv_bfloat16*)(kr + 64 + d * 2)));
            float e = ex2f(s);
            l1 += e;
            #pragma unroll
            for (int d = 0; d < HD_; d++) {
                size_t vi = vtoff + (size_t)d * NN + j;
                o1[d] += e * (__bfloat162float(vh_t[vi]) + __bfloat162float(vl_t[vi]));
            }
        }
        if (hsel == 1) {
            for (int j = NKD; j < NN; j++) {
                const uint8_t* kr = gk + (rowoff + j) * 128;
                float s = 0.f;
                #pragma unroll
                for (int d = 0; d < HD_; d++)
                    s += q[d] * (__bfloat162float(*(const __nv_bfloat16*)(kr + d * 2))
                               + __bfloat162float(*(const __nv_bfloat16*)(kr + 64 + d * 2)));
                float e = ex2f(s);
                l2 += e;
                #pragma unroll
                for (int d = 0; d < HD_; d++) {
                    size_t vi = vtoff + (size_t)d * NN + j;
                    o2[d] += e * (__bfloat162float(vh_t[vi]) + __bfloat162float(vl_t[vi]));
                }
            }
        }
    }
    float* sh = (float*)smem;
    float* shl = sh + 128 * HD_;
    float* sh2 = shl + 128;
    float* sh2l = sh2 + 128 * HD_;
    if (hsel == 1) {
        int r = tid & 127;
        #pragma unroll
        for (int d = 0; d < HD_; d++) { sh[r * HD_ + d] = o1[d]; sh2[r * HD_ + d] = o2[d]; }
        shl[r] = l1; sh2l[r] = l2;
    }
    __syncthreads();
    if (hsel == 0 && active) {
        int r = tid & 127;
        float lt = l1 + shl[r];
        float inv1 = 1.f / lt;
        float inv2 = 1.f / sh2l[r];
        float* orow = ao + ((size_t)(b * NN + qi)) * 256 + h * HD_;
        #pragma unroll
        for (int d = 0; d < HD_; d++)
            orow[d] = (o1[d] + sh[r * HD_ + d]) * inv1 + sh2[r * HD_ + d] * inv2;
    }
#endif
}

// ---------------- launch ----------------
extern "C" void kernel_launch(void* const* d_in, const int* in_sizes, int n_in,
                              void* d_out, int out_size)
{
    const float* q    = (const float*)d_in[0];
    const float* k    = (const float*)d_in[1];
    const float* v    = (const float*)d_in[2];
    const float* fimg = (const float*)d_in[3];
    const float* ftxt = (const float*)d_in[4];
    const float* Wq   = (const float*)d_in[5];
    const float* bq   = (const float*)d_in[6];
    const float* Wk   = (const float*)d_in[7];
    const float* bk   = (const float*)d_in[8];
    const float* Wv   = (const float*)d_in[9];
    const float* bv   = (const float*)d_in[10];
    const float* Wo   = (const float*)d_in[11];
    const float* bo   = (const float*)d_in[12];
    float* out = (float*)d_out;

    uint8_t *gq, *gk;
    __nv_bfloat16 *gvh, *gvl;
    float* ao;
    cudaGetSymbolAddress((void**)&gq, g_q);
    cudaGetSymbolAddress((void**)&gk, g_k);
    cudaGetSymbolAddress((void**)&gvh, g_vh);
    cudaGetSymbolAddress((void**)&gvl, g_vl);
    cudaGetSymbolAddress((void**)&ao, g_ao);

    cudaFuncSetAttribute(gemm_tc, cudaFuncAttributeMaxDynamicSharedMemorySize, GS_TOTAL);
    cudaFuncSetAttribute(attn_kernel, cudaFuncAttributeMaxDynamicSharedMemorySize, SMEM_TOTAL);

    gemm_tc<<<dim3(MT, 3), 256, GS_TOTAL>>>(
        q, k, v, Wq, Wk, Wv, bq, bk, bv,
        gq, gk, gvh, gvl, nullptr, 1, fimg, ftxt);

    dim3 ga(33, H_, BB);
    attn_kernel<<<ga, 256, SMEM_TOTAL>>>(gq, gk, gvh, gvl, ao);

    gemm_tc<<<dim3(MT, 1), 256, GS_TOTAL>>>(
        ao, nullptr, nullptr, Wo, nullptr, nullptr, bo, nullptr, nullptr,
        gq, gk, gvh, gvl, out, 0, fimg, ftxt);
}

// round 17
// speedup vs baseline: 3.2135x; 1.2893x over previous
#include <cuda_runtime.h>
#include <cuda_bf16.h>
#include <cuda_fp16.h>
#include <stdint.h>
#include <math.h>

#define D_    256
#define H_    8
#define HD_   32
#define NIMG_ 4096
#define NN    4112
#define BB    2
#define NKE_  64
#define MROWS (BB * NN)      /* 8224 */
#define NKD   (NN - NKE_)    /* 4048 */
#define NT1   32             /* ceil(4048/128) */
#define NTALL 33             /* 32 dense tiles + 1 mem tile */
#define MT    65             /* ceil(8224/128) GEMM row tiles */

// ---------------- global scratch (no allocs allowed) ----------------
// Q/K packed: per (b,h,n) one 128B row: hi bf16 d0..31 at [0,64), lo at [64,128)
__device__ uint8_t g_q[(size_t)BB * H_ * NN * 128];
__device__ uint8_t g_k[(size_t)BB * H_ * NN * 128];
// V transposed, fp16 single plane: [b][h][d][key]
__device__ __half g_v[(size_t)BB * H_ * HD_ * NN];
__device__ float g_ao[(size_t)MROWS * D_];

// scale: 1/sqrt(32) * log2(e)  (so softmax exp == exp2)
#define QSCALE (0.17677669529663687f * 1.4426950408889634f)

// idesc kind::f16: dtypeF32(1<<4) | atype<<7 | btype<<10 | (N/8)<<17 | (M/16)<<24
// bf16 = 1, fp16 = 0
#define IDESC_128     0x8200490u  /* M=128 N=128, bf16 x bf16 */
#define IDESC_PV_F16  0x8080010u  /* M=128 N=32,  fp16 x fp16 */

// ---------------- arch-portable helpers ----------------
__device__ __forceinline__ uint32_t smem_u32(const void* p) {
    uint32_t a;
    asm("{ .reg .u64 t; cvta.to.shared.u64 t, %1; cvt.u32.u64 %0, t; }" : "=r"(a) : "l"(p));
    return a;
}
__device__ __forceinline__ float ex2f(float x) {
    float y; asm("ex2.approx.ftz.f32 %0, %1;" : "=f"(y) : "f"(x)); return y;
}
__device__ __forceinline__ uint32_t swz(uint32_t b) { return b ^ ((b >> 3) & 0x70); }
__device__ __forceinline__ uint32_t pack_bf(float hi, float lo) {
    uint32_t r; asm("cvt.rn.bf16x2.f32 %0, %1, %2;" : "=r"(r) : "f"(hi), "f"(lo)); return r;
}
// pack two floats to fp16x2 ('lo' ends up in low 16 bits)
__device__ __forceinline__ uint32_t pack_h16(float lo, float hi) {
    __half2 h = __floats2half2_rn(lo, hi);
    return *reinterpret_cast<uint32_t*>(&h);
}

// ---------------- tcgen05 helpers: sm_103a ONLY ----------------
#if defined(__CUDA_ARCH_FEAT_SM103_ALL)
__device__ __forceinline__ bool elect1() {
    uint32_t p;
    asm volatile("{ .reg .pred p; elect.sync _|p, 0xFFFFFFFF; selp.b32 %0, 1, 0, p; }" : "=r"(p));
    return p != 0;
}
__device__ __forceinline__ uint64_t mkdesc(uint32_t addr) {
    return ((uint64_t)2 << 61) | ((uint64_t)1 << 46) | ((uint64_t)64 << 32)
         | ((uint64_t)1 << 16) | ((addr >> 4) & 0x3FFF);
}
__device__ __forceinline__ void mma_ss(uint32_t d, uint64_t a, uint64_t b, uint32_t idesc, bool acc) {
    uint32_t en = acc ? 1u : 0u;
    asm volatile(
        "{\n\t.reg .pred p;\n\tsetp.ne.u32 p, %5, 0;\n\t"
        "tcgen05.mma.cta_group::1.kind::f16 [%0], %1, %2, %3, {%4,%4,%4,%4}, p;\n\t}"
        :: "r"(d), "l"(a), "l"(b), "r"(idesc), "r"(0u), "r"(en) : "memory");
}
#define TC_COMMIT(mbar) \
    asm volatile("tcgen05.commit.cta_group::1.mbarrier::arrive::one.shared::cluster.b64 [%0];" :: "r"(mbar) : "memory")
#define TC_ALLOC(smem_addr, n) \
    asm volatile("tcgen05.alloc.cta_group::1.sync.aligned.shared::cta.b32 [%0], %1;" :: "r"(smem_addr), "r"(n) : "memory")
#define TC_DEALLOC(tmem, n) \
    asm volatile("tcgen05.dealloc.cta_group::1.sync.aligned.b32 %0, %1;" :: "r"(tmem), "r"(n))
#define TC_RELINQ() asm volatile("tcgen05.relinquish_alloc_permit.cta_group::1.sync.aligned;")
#define TC_WAIT_LD() asm volatile("tcgen05.wait::ld.sync.aligned;" ::: "memory")
#define TC_FENCE_AFTER() asm volatile("tcgen05.fence::after_thread_sync;" ::: "memory")
#define TC_FENCE_BEFORE() asm volatile("tcgen05.fence::before_thread_sync;" ::: "memory")
#define FENCE_ASYNC() asm volatile("fence.proxy.async.shared::cta;" ::: "memory")
#define MB_INIT(addr, cnt) \
    asm volatile("mbarrier.init.shared.b64 [%0], %1;" :: "r"(addr), "r"(cnt) : "memory")

__device__ __forceinline__ void mb_wait(uint32_t mbar, uint32_t parity) {
    uint32_t done;
    asm volatile(
        "{\n\t.reg .pred p;\n\t"
        "mbarrier.try_wait.parity.acquire.cta.shared::cta.b64 p, [%1], %2;\n\t"
        "selp.b32 %0, 1, 0, p;\n\t}"
        : "=r"(done) : "r"(mbar), "r"(parity) : "memory");
    if (!done) {
        asm volatile(
            "{\n\t.reg .pred P1;\n\t"
            "WL_%=:\n\t"
            "mbarrier.try_wait.parity.acquire.cta.shared::cta.b64 P1, [%0], %1, 0x989680;\n\t"
            "@P1 bra.uni WD_%=;\n\t"
            "bra.uni WL_%=;\n\t"
            "WD_%=:\n\t}"
            :: "r"(mbar), "r"(parity) : "memory");
    }
}

#define LDTM_X32(r, addr) \
    asm volatile( \
        "tcgen05.ld.sync.aligned.32x32b.x32.b32 " \
        "{%0,%1,%2,%3,%4,%5,%6,%7,%8,%9,%10,%11,%12,%13,%14,%15," \
        "%16,%17,%18,%19,%20,%21,%22,%23,%24,%25,%26,%27,%28,%29,%30,%31}, [%32];" \
        : "=r"((r)[0]),"=r"((r)[1]),"=r"((r)[2]),"=r"((r)[3]),"=r"((r)[4]),"=r"((r)[5]), \
          "=r"((r)[6]),"=r"((r)[7]),"=r"((r)[8]),"=r"((r)[9]),"=r"((r)[10]),"=r"((r)[11]), \
          "=r"((r)[12]),"=r"((r)[13]),"=r"((r)[14]),"=r"((r)[15]),"=r"((r)[16]),"=r"((r)[17]), \
          "=r"((r)[18]),"=r"((r)[19]),"=r"((r)[20]),"=r"((r)[21]),"=r"((r)[22]),"=r"((r)[23]), \
          "=r"((r)[24]),"=r"((r)[25]),"=r"((r)[26]),"=r"((r)[27]),"=r"((r)[28]),"=r"((r)[29]), \
          "=r"((r)[30]),"=r"((r)[31]) : "r"(addr))
#endif  // __CUDA_ARCH_FEAT_SM103_ALL

// ================= tcgen05 projection GEMM (2 CTAs/SM; mode-3 now fp16 V) ==========
#define GS_AH   0        /* 16384 */
#define GS_AL   16384    /* 16384 */
#define GS_WH   32768    /* 32768 */
#define GS_WL   65536    /* 32768 */
#define GS_BIAS 98304    /* 1024 */
#define GS_TM   99328
#define GS_MB   99336
#define GS_TOTAL 99456

__global__ void __launch_bounds__(256, 2) gemm_tc(
    const float* __restrict__ A0, const float* __restrict__ A1, const float* __restrict__ A2,
    const float* __restrict__ W0, const float* __restrict__ W1, const float* __restrict__ W2,
    const float* __restrict__ B0, const float* __restrict__ B1, const float* __restrict__ B2,
    uint8_t* __restrict__ gq, uint8_t* __restrict__ gk,
    __half* __restrict__ gv,
    float* __restrict__ outf, int qkv,
    const float* __restrict__ fimg, const float* __restrict__ ftxt)
{
    extern __shared__ __align__(1024) char smem[];
    const int tid = threadIdx.x;
    const int m0 = blockIdx.x * 128;
    int mode;
    const float *A, *W, *bias;
    if (qkv) {
        mode = blockIdx.y + 1;
        if (blockIdx.y == 0)      { A = A0; W = W0; bias = B0; }
        else if (blockIdx.y == 1) { A = A1; W = W1; bias = B1; }
        else                      { A = A2; W = W2; bias = B2; }
    } else { mode = 0; A = A0; W = W0; bias = B0; }

#if defined(__CUDA_ARCH_FEAT_SM103_ALL)
    const uint32_t sb = smem_u32(smem);
    const int wid = tid >> 5;
    const int lane = tid & 31;

    if (wid == 0) TC_ALLOC(sb + GS_TM, 256);
    if (tid == 0) MB_INIT(sb + GS_MB, 1);
    __syncthreads();
    uint32_t tmem;
    asm volatile("ld.shared.b32 %0, [%1];" : "=r"(tmem) : "r"(sb + GS_TM));

    if (tid < 256) *(float*)(smem + GS_BIAS + tid * 4) = bias[tid];

    uint32_t par = 0;
    for (int c = 0; c < 4; c++) {
        if (c > 0) { mb_wait(sb + GS_MB, par); par ^= 1; }
        const int k0 = c * 64;
        #pragma unroll
        for (int it = 0; it < 8; it++) {
            int i = tid + it * 256;
            int r = i >> 4;
            int c4 = (i & 15) * 4;
            float4 va = make_float4(0.f, 0.f, 0.f, 0.f);
            if (m0 + r < MROWS) va = *(const float4*)(A + (size_t)(m0 + r) * 256 + k0 + c4);
            uint32_t h01 = pack_bf(va.y, va.x);
            uint32_t h23 = pack_bf(va.w, va.z);
            float hx = __uint_as_float(h01 << 16), hy = __uint_as_float(h01 & 0xFFFF0000u);
            float hz = __uint_as_float(h23 << 16), hw = __uint_as_float(h23 & 0xFFFF0000u);
            uint32_t l01 = pack_bf(va.y - hy, va.x - hx);
            uint32_t l23 = pack_bf(va.w - hw, va.z - hz);
            uint32_t off = swz((uint32_t)(r * 128 + c4 * 2));
            *(uint2*)(smem + GS_AH + off) = make_uint2(h01, h23);
            *(uint2*)(smem + GS_AL + off) = make_uint2(l01, l23);
        }
        #pragma unroll
        for (int it = 0; it < 16; it++) {
            int i = tid + it * 256;
            int r = i >> 4;
            int c4 = (i & 15) * 4;
            float4 vw = *(const float4*)(W + (size_t)r * 256 + k0 + c4);
            uint32_t h01 = pack_bf(vw.y, vw.x);
            uint32_t h23 = pack_bf(vw.w, vw.z);
            float hx = __uint_as_float(h01 << 16), hy = __uint_as_float(h01 & 0xFFFF0000u);
            float hz = __uint_as_float(h23 << 16), hw = __uint_as_float(h23 & 0xFFFF0000u);
            uint32_t l01 = pack_bf(vw.y - hy, vw.x - hx);
            uint32_t l23 = pack_bf(vw.w - hw, vw.z - hz);
            uint32_t off = swz((uint32_t)(r * 128 + c4 * 2));
            *(uint2*)(smem + GS_WH + off) = make_uint2(h01, h23);
            *(uint2*)(smem + GS_WL + off) = make_uint2(l01, l23);
        }
        FENCE_ASYNC();
        __syncthreads();
        if (wid == 0 && elect1()) {
            uint64_t ah = mkdesc(sb + GS_AH), al = mkdesc(sb + GS_AL);
            uint64_t wh = mkdesc(sb + GS_WH), wl = mkdesc(sb + GS_WL);
            #pragma unroll
            for (int nh = 0; nh < 2; nh++) {
                uint32_t dcol = tmem + nh * 128;
                uint64_t bo = (uint64_t)nh * 1024;
                #pragma unroll
                for (int ks = 0; ks < 4; ks++) {
                    uint64_t a_h = ah + 2 * ks, a_l = al + 2 * ks;
                    uint64_t b_h = wh + bo + 2 * ks, b_l = wl + bo + 2 * ks;
                    mma_ss(dcol, a_h, b_h, IDESC_128, !(c == 0 && ks == 0));
                    mma_ss(dcol, a_h, b_l, IDESC_128, true);
                    mma_ss(dcol, a_l, b_h, IDESC_128, true);
                }
            }
            TC_COMMIT(sb + GS_MB);
        }
    }
    mb_wait(sb + GS_MB, par);
    TC_FENCE_AFTER();

    {
        const int r = (wid & 3) * 32 + lane;
        const int m = m0 + r;
        const int cb0 = (wid >> 2) * 128;
        const bool mok = (m < MROWS);
        int bb = (m >= NN) ? 1 : 0;
        int n = m - bb * NN;
        float2 fr[16];
        if (mok && (mode == 1 || mode == 2)) {
            const float* fbase = (n < NIMG_) ? (fimg + (size_t)n * 32)
                                             : (ftxt + (size_t)(n - NIMG_) * 32);
            #pragma unroll
            for (int i = 0; i < 8; i++) {
                float4 t = *(const float4*)(fbase + i * 4);
                fr[2 * i]     = make_float2(t.x, t.y);
                fr[2 * i + 1] = make_float2(t.z, t.w);
            }
        }
        #pragma unroll
        for (int cc = 0; cc < 4; cc++) {
            const int c0 = cb0 + cc * 32;
            uint32_t s[32];
            LDTM_X32(s, tmem + c0);
            TC_WAIT_LD();
            if (!mok) continue;
            if (mode == 0) {
                #pragma unroll
                for (int j = 0; j < 32; j++) {
                    float bv = *(const float*)(smem + GS_BIAS + (c0 + j) * 4);
                    outf[(size_t)m * 256 + c0 + j] = __uint_as_float(s[j]) + bv;
                }
            } else if (mode == 3) {
                const int head = c0 >> 5;
                #pragma unroll
                for (int j = 0; j < 32; j++) {
                    float bv = *(const float*)(smem + GS_BIAS + (c0 + j) * 4);
                    float val = __uint_as_float(s[j]) + bv;
                    size_t dst = ((size_t)(bb * H_ + head) * HD_ + j) * NN + n;
                    gv[dst] = __float2half(val);
                }
            } else {
                const int head = c0 >> 5;
                uint8_t* gout = (mode == 1) ? gq : gk;
                uint8_t* rowp = gout + ((size_t)(bb * H_ + head) * NN + n) * 128;
                #pragma unroll
                for (int p = 0; p < 16; p++) {
                    float b0v = *(const float*)(smem + GS_BIAS + (c0 + 2 * p) * 4);
                    float b1v = *(const float*)(smem + GS_BIAS + (c0 + 2 * p + 1) * 4);
                    float x0 = __uint_as_float(s[2 * p]) + b0v;
                    float x1 = __uint_as_float(s[2 * p + 1]) + b1v;
                    float y0 = x0 * fr[p].x - x1 * fr[p].y;
                    float y1 = x0 * fr[p].y + x1 * fr[p].x;
                    if (mode == 1) { y0 *= QSCALE; y1 *= QSCALE; }
                    uint32_t hp = pack_bf(y1, y0);
                    float h0 = __uint_as_float(hp << 16);
                    float h1 = __uint_as_float(hp & 0xFFFF0000u);
                    uint32_t lp = pack_bf(y1 - h1, y0 - h0);
                    *(uint32_t*)(rowp + p * 4) = hp;
                    *(uint32_t*)(rowp + 64 + p * 4) = lp;
                }
            }
        }
    }
    __syncthreads();
    if (wid == 0) {
        TC_RELINQ();
        TC_DEALLOC(tmem, 256);
    }
#else
    for (int idx = tid; idx < 128 * 128; idx += 256) {
        int r = idx >> 7;
        int p = idx & 127;
        int m = m0 + r;
        if (m >= MROWS) continue;
        int j0_ = p * 2;
        float s0 = bias[j0_], s1 = bias[j0_ + 1];
        for (int k2 = 0; k2 < 256; k2++) {
            float a = A[(size_t)m * 256 + k2];
            s0 += a * W[(size_t)j0_ * 256 + k2];
            s1 += a * W[(size_t)(j0_ + 1) * 256 + k2];
        }
        int bb = (m >= NN) ? 1 : 0;
        int n = m - bb * NN;
        if (mode == 1 || mode == 2) {
            int cidx = (j0_ & 31) >> 1;
            const float* f = (n < NIMG_) ? (fimg + ((size_t)n * 16 + cidx) * 2)
                                         : (ftxt + ((size_t)(n - NIMG_) * 16 + cidx) * 2);
            float y0 = s0 * f[0] - s1 * f[1];
            float y1 = s0 * f[1] + s1 * f[0];
            if (mode == 1) { y0 *= QSCALE; y1 *= QSCALE; }
            int head = j0_ >> 5, d = j0_ & 31;
            uint8_t* gout = (mode == 1) ? gq : gk;
            uint8_t* rowp = gout + ((size_t)(bb * H_ + head) * NN + n) * 128;
            uint32_t hp = pack_bf(y1, y0);
            float h0 = __uint_as_float(hp << 16), h1 = __uint_as_float(hp & 0xFFFF0000u);
            uint32_t lp = pack_bf(y1 - h1, y0 - h0);
            *(uint32_t*)(rowp + (d >> 1) * 4) = hp;
            *(uint32_t*)(rowp + 64 + (d >> 1) * 4) = lp;
        } else if (mode == 3) {
            int head = j0_ >> 5, d = j0_ & 31;
            #pragma unroll
            for (int e = 0; e < 2; e++) {
                float val = e ? s1 : s0;
                size_t dst = ((size_t)(bb * H_ + head) * HD_ + d + e) * NN + n;
                gv[dst] = __float2half(val);
            }
        } else {
            outf[(size_t)m * 256 + j0_] = s0;
            outf[(size_t)m * 256 + j0_ + 1] = s1;
        }
    }
#endif
}

// ========== attention: fp16 P single-plane, fp16 V, double-buffered P, late MBO ======
#define SM_Q     0
#define SM_KV0   16384
#define KV_STRIDE 32768
#define KV_VOFF  16384      /* V fp16 at +16384, 8KB used */
#define SM_P0    147456     /* 32KB fp16 */
#define SM_P1    180224     /* 32KB */
#define SM_TM    212992
#define SM_MBS   213000
#define SM_MBO   213008
#define SM_LSUM1 213056
#define SM_LSUM2 213568
#define SMEM_TOTAL 214080

#define TM_S0 0
#define TM_S1 128
#define TM_O1 256
#define TM_O2 288

#if defined(__CUDA_ARCH_FEAT_SM103_ALL)
__device__ __forceinline__ void load_rows_packed(
    char* dst, const uint8_t* gpk, int valid, int tid)
{
    #pragma unroll
    for (int it = 0; it < 4; it++) {
        int f = tid + it * 256;
        int r = f >> 3;
        int cb = (f & 7) * 16;
        uint4 x = make_uint4(0, 0, 0, 0);
        if (r < valid) x = *(const uint4*)(gpk + (size_t)r * 128 + cb);
        *(uint4*)(dst + swz((uint32_t)(r * 128 + cb))) = x;
    }
}

// Vt fp16 tile: 32 d-rows x 128 keys, blocked SW128 atoms (8KB).
__device__ __forceinline__ void load_vt(
    char* dst, const __half* gv_t, int valid, int tid)
{
    #pragma unroll
    for (int it = 0; it < 2; it++) {
        int c = tid + it * 256;
        int d = c >> 4;
        int kc = c & 15;
        uint4 x = make_uint4(0, 0, 0, 0);
        if (kc * 8 < valid) x = *(const uint4*)(gv_t + (size_t)d * NN + kc * 8);
        uint32_t off = swz((uint32_t)((d >> 3) * 1024 + (kc >> 3) * 4096
                                      + (d & 7) * 128 + (kc & 7) * 16));
        *(uint4*)(dst + off) = x;
    }
}

__device__ __forceinline__ void load_kv(
    char* smem, int buf, const uint8_t* gk_rows,
    const __half* gv_t, size_t vtoff, int kbase, int valid, int tid)
{
    char* kb = smem + SM_KV0 + buf * KV_STRIDE;
    load_rows_packed(kb, gk_rows + (size_t)kbase * 128, valid, tid);
    load_vt(kb + KV_VOFF, gv_t + vtoff + kbase, valid, tid);
}

__device__ __forceinline__ void issue_qk(uint32_t qb, uint32_t kb, uint32_t tmem_d) {
    uint64_t qd = mkdesc(qb);
    uint64_t kd = mkdesc(kb);
    mma_ss(tmem_d, qd + 0, kd + 0, IDESC_128, false);
    mma_ss(tmem_d, qd + 2, kd + 2, IDESC_128, true);
    mma_ss(tmem_d, qd + 0, kd + 4, IDESC_128, true);
    mma_ss(tmem_d, qd + 2, kd + 6, IDESC_128, true);
    mma_ss(tmem_d, qd + 4, kd + 0, IDESC_128, true);
    mma_ss(tmem_d, qd + 6, kd + 2, IDESC_128, true);
}

// PV fp16 x fp16, single term: 8 MMAs
__device__ __forceinline__ void issue_pv(uint32_t pb, uint32_t vb, uint32_t tmem_d, bool first) {
    uint64_t ap = mkdesc(pb);
    uint64_t bv = mkdesc(vb);
    #pragma unroll
    for (int ks = 0; ks < 8; ks++) {
        uint64_t ad = ap + (ks < 4 ? 2 * ks : 1024 + 2 * (ks - 4));
        uint64_t bd = bv + (ks < 4 ? 2 * ks : 256 + 2 * (ks - 4));
        mma_ss(tmem_d, ad, bd, IDESC_PV_F16, !(first && ks == 0));
    }
}

// Softmax epilogue: exp, l-accumulate, fp16 P, STS.128.
__device__ __forceinline__ void epilogue_tile(
    char* smem, uint32_t pbase, uint32_t tmem_s, int row, int half, int valid, float& lacc)
{
    const uint32_t xorc = (uint32_t)((row & 7) << 4);
    const uint32_t base0 = (uint32_t)((row >> 3) * 1024 + (row & 7) * 128);
    #pragma unroll
    for (int cc = 0; cc < 2; cc++) {
        const int c0 = half * 64 + cc * 32;
        uint32_t sreg[32];
        LDTM_X32(sreg, tmem_s + c0);
        TC_WAIT_LD();
        const uint32_t cbase = base0 + (uint32_t)((c0 >> 6) * 16384);
        const uint32_t kk0 = (uint32_t)((c0 & 63) * 2);
        if (valid >= c0 + 32) {
            #pragma unroll
            for (int g = 0; g < 4; g++) {
                float e[8];
                #pragma unroll
                for (int j = 0; j < 8; j++) {
                    e[j] = ex2f(__uint_as_float(sreg[g * 8 + j]));
                    lacc += e[j];
                }
                uint4 hv;
                hv.x = pack_h16(e[0], e[1]);
                hv.y = pack_h16(e[2], e[3]);
                hv.z = pack_h16(e[4], e[5]);
                hv.w = pack_h16(e[6], e[7]);
                *(uint4*)(smem + pbase + cbase + ((kk0 + g * 16) ^ xorc)) = hv;
            }
        } else {
            #pragma unroll
            for (int g = 0; g < 4; g++) {
                float e[8];
                #pragma unroll
                for (int j = 0; j < 8; j++) {
                    int col = c0 + g * 8 + j;
                    e[j] = (col < valid) ? ex2f(__uint_as_float(sreg[g * 8 + j])) : 0.f;
                    lacc += e[j];
                }
                uint4 hv;
                hv.x = pack_h16(e[0], e[1]);
                hv.y = pack_h16(e[2], e[3]);
                hv.z = pack_h16(e[4], e[5]);
                hv.w = pack_h16(e[6], e[7]);
                *(uint4*)(smem + pbase + cbase + ((kk0 + g * 16) ^ xorc)) = hv;
            }
        }
    }
}
#endif  // __CUDA_ARCH_FEAT_SM103_ALL

__global__ void __launch_bounds__(256, 1) attn_kernel(
    const uint8_t* __restrict__ gq, const uint8_t* __restrict__ gk,
    const __half* __restrict__ gv_t, float* __restrict__ ao)
{
    extern __shared__ __align__(1024) char smem[];
    const int tid = threadIdx.x;
    const int b = blockIdx.z, h = blockIdx.y;
    const size_t rowoff = (size_t)(b * H_ + h) * NN;
    const size_t vtoff = (size_t)(b * H_ + h) * HD_ * NN;
    const int q0 = blockIdx.x * 128;
    const int qvalid = min(128, NN - q0);

#if defined(__CUDA_ARCH_FEAT_SM103_ALL)
    const uint32_t sbase = smem_u32(smem);
    const int wid = tid >> 5;
    const int lane = tid & 31;
    const int half = wid >> 2;
    const int row = (wid & 3) * 32 + lane;
    const uint8_t* gk_rows = gk + rowoff * 128;

    if (wid == 0) TC_ALLOC(sbase + SM_TM, 512);
    if (tid == 0) { MB_INIT(sbase + SM_MBS, 1); MB_INIT(sbase + SM_MBO, 1); }
    __syncthreads();
    uint32_t tmem;
    asm volatile("ld.shared.b32 %0, [%1];" : "=r"(tmem) : "r"(sbase + SM_TM));

    load_rows_packed(smem + SM_Q, gq + (rowoff + q0) * 128, qvalid, tid);
    load_kv(smem, 0, gk_rows, gv_t, vtoff, 0, 128, tid);
    load_kv(smem, 1, gk_rows, gv_t, vtoff, 128, 128, tid);
    FENCE_ASYNC();
    __syncthreads();
    if (wid == 0 && elect1()) {
        issue_qk(sbase + SM_Q, sbase + SM_KV0, tmem + TM_S0);
        TC_COMMIT(sbase + SM_MBS);
    }

    uint32_t pS = 0, pO = 0;
    float lacc1 = 0.f, lacc2 = 0.f;

    for (int t = 0; t < NTALL; t++) {
        const int valid = (t < NT1) ? min(128, NKD - t * 128) : NKE_;
        mb_wait(sbase + SM_MBS, pS); pS ^= 1;
        TC_FENCE_AFTER();
        if (t + 1 < NTALL && wid == 0 && elect1()) {
            issue_qk(sbase + SM_Q, sbase + SM_KV0 + ((t + 1) & 3) * KV_STRIDE,
                     tmem + (((t + 1) & 1) ? TM_S1 : TM_S0));
            TC_COMMIT(sbase + SM_MBS);
        }
        if (t + 2 < NTALL) {
            int nb = (t + 2 < NT1) ? (t + 2) * 128 : NKD;
            int nv = (t + 2 < NT1) ? min(128, NKD - nb) : NKE_;
            load_kv(smem, (t + 2) & 3, gk_rows, gv_t, vtoff, nb, nv, tid);
        }
        // epilogue writes P[t&1]; PV(t-1) reads P[(t-1)&1] concurrently
        epilogue_tile(smem, (t & 1) ? SM_P1 : SM_P0,
                      tmem + ((t & 1) ? TM_S1 : TM_S0), row, half, valid,
                      (t < NT1) ? lacc1 : lacc2);
        TC_FENCE_BEFORE();
        FENCE_ASYNC();
        __syncthreads();
        // late MBO wait: PV(t-1) drained under the epilogue
        if (t >= 1) { mb_wait(sbase + SM_MBO, pO); pO ^= 1; TC_FENCE_AFTER(); }
        if (wid == 0 && elect1()) {
            issue_pv(sbase + ((t & 1) ? SM_P1 : SM_P0),
                     sbase + SM_KV0 + (t & 3) * KV_STRIDE + KV_VOFF,
                     tmem + ((t < NT1) ? TM_O1 : TM_O2),
                     (t == 0) || (t == NT1));
            TC_COMMIT(sbase + SM_MBO);
        }
    }

    float* lsum1 = (float*)(smem + SM_LSUM1);
    float* lsum2 = (float*)(smem + SM_LSUM2);
    if (half == 1) { lsum1[row] = lacc1; lsum2[row] = lacc2; }
    __syncthreads();

    mb_wait(sbase + SM_MBO, pO); pO ^= 1;
    TC_FENCE_AFTER();
    if (half == 0) {
        float l1 = lacc1 + lsum1[row];
        float l2 = lacc2 + lsum2[row];
        uint32_t o1[32], o2[32];
        LDTM_X32(o1, tmem + TM_O1);
        LDTM_X32(o2, tmem + TM_O2);
        TC_WAIT_LD();
        float inv1 = 1.f / l1, inv2 = 1.f / l2;
        if (row < qvalid) {
            float* orow = ao + ((size_t)(b * NN + q0 + row)) * 256 + h * 32;
            #pragma unroll
            for (int d = 0; d < 32; d += 4) {
                float4 tv;
                tv.x = __uint_as_float(o1[d])     * inv1 + __uint_as_float(o2[d])     * inv2;
                tv.y = __uint_as_float(o1[d + 1]) * inv1 + __uint_as_float(o2[d + 1]) * inv2;
                tv.z = __uint_as_float(o1[d + 2]) * inv1 + __uint_as_float(o2[d + 2]) * inv2;
                tv.w = __uint_as_float(o1[d + 3]) * inv1 + __uint_as_float(o2[d + 3]) * inv2;
                *(float4*)(orow + d) = tv;
            }
        }
    }
    __syncthreads();
    if (wid == 0) {
        TC_RELINQ();
        TC_DEALLOC(tmem, 512);
    }
#else
    // scalar fallback
    const int qi = q0 + (tid & 127);
    const int hsel = tid >> 7;
    const bool active = qi < NN;

    float q[HD_];
    if (active) {
        const uint8_t* qr = gq + (rowoff + qi) * 128;
        #pragma unroll
        for (int d = 0; d < HD_; d++)
            q[d] = __bfloat162float(*(const __nv_bfloat16*)(qr + d * 2))
                 + __bfloat162float(*(const __nv_bfloat16*)(qr + 64 + d * 2));
    } else {
        #pragma unroll
        for (int d = 0; d < HD_; d++) q[d] = 0.f;
    }

    float o1[HD_] = {}, o2[HD_] = {};
    float l1 = 0.f, l2 = 0.f;
    const int ks = hsel ? 2048 : 0;
    const int ke = hsel ? NKD : 2048;
    if (active) {
        for (int j = ks; j < ke; j++) {
            const uint8_t* kr = gk + (rowoff + j) * 128;
            float s = 0.f;
            #pragma unroll
            for (int d = 0; d < HD_; d++)
                s += q[d] * (__bfloat162float(*(const __nv_bfloat16*)(kr + d * 2))
                           + __bfloat162float(*(const __nv_bfloat16*)(kr + 64 + d * 2)));
            float e = ex2f(s);
            l1 += e;
            #pragma unroll
            for (int d = 0; d < HD_; d++)
                o1[d] += e * __half2float(gv_t[vtoff + (size_t)d * NN + j]);
        }
        if (hsel == 1) {
            for (int j = NKD; j < NN; j++) {
                const uint8_t* kr = gk + (rowoff + j) * 128;
                float s = 0.f;
                #pragma unroll
                for (int d = 0; d < HD_; d++)
                    s += q[d] * (__bfloat162float(*(const __nv_bfloat16*)(kr + d * 2))
                               + __bfloat162float(*(const __nv_bfloat16*)(kr + 64 + d * 2)));
                float e = ex2f(s);
                l2 += e;
                #pragma unroll
                for (int d = 0; d < HD_; d++)
                    o2[d] += e * __half2float(gv_t[vtoff + (size_t)d * NN + j]);
            }
        }
    }
    float* sh = (float*)smem;
    float* shl = sh + 128 * HD_;
    float* sh2 = shl + 128;
    float* sh2l = sh2 + 128 * HD_;
    if (hsel == 1) {
        int r = tid & 127;
        #pragma unroll
        for (int d = 0; d < HD_; d++) { sh[r * HD_ + d] = o1[d]; sh2[r * HD_ + d] = o2[d]; }
        shl[r] = l1; sh2l[r] = l2;
    }
    __syncthreads();
    if (hsel == 0 && active) {
        int r = tid & 127;
        float lt = l1 + shl[r];
        float inv1 = 1.f / lt;
        float inv2 = 1.f / sh2l[r];
        float* orow = ao + ((size_t)(b * NN + qi)) * 256 + h * HD_;
        #pragma unroll
        for (int d = 0; d < HD_; d++)
            orow[d] = (o1[d] + sh[r * HD_ + d]) * inv1 + sh2[r * HD_ + d] * inv2;
    }
#endif
}

// ---------------- launch ----------------
extern "C" void kernel_launch(void* const* d_in, const int* in_sizes, int n_in,
                              void* d_out, int out_size)
{
    const float* q    = (const float*)d_in[0];
    const float* k    = (const float*)d_in[1];
    const float* v    = (const float*)d_in[2];
    const float* fimg = (const float*)d_in[3];
    const float* ftxt = (const float*)d_in[4];
    const float* Wq   = (const float*)d_in[5];
    const float* bq   = (const float*)d_in[6];
    const float* Wk   = (const float*)d_in[7];
    const float* bk   = (const float*)d_in[8];
    const float* Wv   = (const float*)d_in[9];
    const float* bv   = (const float*)d_in[10];
    const float* Wo   = (const float*)d_in[11];
    const float* bo   = (const float*)d_in[12];
    float* out = (float*)d_out;

    uint8_t *gq, *gk;
    __half* gv;
    float* ao;
    cudaGetSymbolAddress((void**)&gq, g_q);
    cudaGetSymbolAddress((void**)&gk, g_k);
    cudaGetSymbolAddress((void**)&gv, g_v);
    cudaGetSymbolAddress((void**)&ao, g_ao);

    cudaFuncSetAttribute(gemm_tc, cudaFuncAttributeMaxDynamicSharedMemorySize, GS_TOTAL);
    cudaFuncSetAttribute(attn_kernel, cudaFuncAttributeMaxDynamicSharedMemorySize, SMEM_TOTAL);

    gemm_tc<<<dim3(MT, 3), 256, GS_TOTAL>>>(
        q, k, v, Wq, Wk, Wv, bq, bk, bv,
        gq, gk, gv, nullptr, 1, fimg, ftxt);

    dim3 ga(33, H_, BB);
    attn_kernel<<<ga, 256, SMEM_TOTAL>>>(gq, gk, gv, ao);

    gemm_tc<<<dim3(MT, 1), 256, GS_TOTAL>>>(
        ao, nullptr, nullptr, Wo, nullptr, nullptr, bo, nullptr, nullptr,
        gq, gk, gv, out, 0, fimg, ftxt);
}